// round 8
// baseline (speedup 1.0000x reference)
#include <cuda_runtime.h>
#include <math.h>
#include <stdint.h>

#define DIM   192
#define HEADS 6
#define HD    32
#define NWIN  1024          // 4 * 16 * 16
#define NQTOK 65536         // 1024 * 64  (== B*L)
#define NKVTOK 262144       // 1024 * 256
#define SCALE 0.17677669529663687f   // 32^-0.5

// ---------------- scratch (device globals; no runtime allocation) ----------------
__device__ float g_xn [(size_t)NQTOK * DIM];        // LN1 output, window order
__device__ float g_q  [(size_t)NQTOK * DIM];        // q projection, window order
__device__ float g_kv [(size_t)NKVTOK * 2 * DIM];   // k | v, window order
__device__ float g_ao [(size_t)NQTOK * DIM];        // attention output, window order
__device__ float g_x1 [(size_t)NQTOK * DIM];        // x after first residual
__device__ float g_ln2[(size_t)NQTOK * DIM];        // LN2 output
__device__ float g_h  [(size_t)NQTOK * 4 * DIM];    // gelu(fc1) output

// ---------------- helpers ----------------
__device__ __forceinline__ void mma_tf32(float* d, const float* a, const float* b) {
    asm volatile(
        "mma.sync.aligned.m16n8k8.row.col.f32.tf32.tf32.f32 "
        "{%0,%1,%2,%3}, {%4,%5,%6,%7}, {%8,%9}, {%0,%1,%2,%3};\n"
        : "+f"(d[0]), "+f"(d[1]), "+f"(d[2]), "+f"(d[3])
        : "r"(__float_as_uint(a[0])), "r"(__float_as_uint(a[1])),
          "r"(__float_as_uint(a[2])), "r"(__float_as_uint(a[3])),
          "r"(__float_as_uint(b[0])), "r"(__float_as_uint(b[1])));
}

__device__ __forceinline__ void cp16(uint32_t dst, const void* src) {
    asm volatile("cp.async.cg.shared.global [%0], [%1], 16;\n" :: "r"(dst), "l"(src));
}
#define CP_COMMIT() asm volatile("cp.async.commit_group;\n")
#define CP_WAIT1()  asm volatile("cp.async.wait_group 1;\n")
#define CP_WAIT0()  asm volatile("cp.async.wait_group 0;\n")

// ---------------- LayerNorm (one token per block, 192 threads) ----------------
template<int MODE>
__global__ __launch_bounds__(192) void ln_kernel(
    const float* __restrict__ x, const float* __restrict__ w,
    const float* __restrict__ b, float* __restrict__ out)
{
    int tok = blockIdx.x;
    int tid = threadIdx.x;
    int in_row, out_row;
    if (MODE == 0) {
        int win = tok >> 6, t = tok & 63;
        int bb = win >> 8, wi = win & 255;
        int wr = wi >> 4,  wc = wi & 15;
        int r  = t  >> 3,  c  = t  & 7;
        in_row  = bb * 16384 + (wr * 8 + r) * 128 + (wc * 8 + c);
        out_row = tok;
    } else {
        in_row = out_row = tok;
    }
    float v = x[(size_t)in_row * DIM + tid];
    float s1 = v, s2 = v * v;
    #pragma unroll
    for (int off = 16; off; off >>= 1) {
        s1 += __shfl_xor_sync(0xffffffffu, s1, off);
        s2 += __shfl_xor_sync(0xffffffffu, s2, off);
    }
    __shared__ float red[12];
    int warp = tid >> 5, lane = tid & 31;
    if (lane == 0) { red[warp] = s1; red[6 + warp] = s2; }
    __syncthreads();
    if (tid == 0) {
        float a = 0.f, c2 = 0.f;
        #pragma unroll
        for (int i = 0; i < 6; i++) { a += red[i]; c2 += red[6 + i]; }
        red[0] = a; red[6] = c2;
    }
    __syncthreads();
    float mean = red[0] * (1.0f / 192.0f);
    float var  = red[6] * (1.0f / 192.0f) - mean * mean;
    float rstd = rsqrtf(var + 1e-5f);
    out[(size_t)out_row * DIM + tid] = (v - mean) * rstd * w[tid] + b[tid];
}

// ---------------- TF32 GEMM, BM=256, cp.async double-buffered ----------------
// C = A @ W^T + bias.  W is (N, K) row-major.
// MODE 0: plain.  MODE 1: gather A rows through 16x16 window partition of x2.
// MODE 2: + add[nat_row], store window-reversed.  MODE 3: exact gelu.
// MODE 4: + add[row].
#define GEMM_AS  36
#define GEMM_ASZ (256 * GEMM_AS)
#define GEMM_BSZ (64 * GEMM_AS)
#define GEMM_SMEM ((2 * GEMM_ASZ + 2 * GEMM_BSZ) * 4)

template<int MODE, int N, int K>
__global__ __launch_bounds__(256) void gemm_tf32(
    const float* __restrict__ A, const float* __restrict__ W,
    const float* __restrict__ bias, float* __restrict__ C,
    const float* __restrict__ add)
{
    constexpr int BM = 256, BN = 64, BK = 32, AS = GEMM_AS;
    constexpr int ASZ = GEMM_ASZ, BSZ = GEMM_BSZ;
    constexpr int NIT = K / BK;
    extern __shared__ float smg[];
    float* Asm = smg;               // 2 * ASZ
    float* Bsm = smg + 2 * ASZ;     // 2 * BSZ

    int tid = threadIdx.x;
    int mb = blockIdx.x * BM, nb = blockIdx.y * BN;
    int warp = tid >> 5, lane = tid & 31;
    int wm = warp & 3, wn = warp >> 2;         // 4m x 2n warp grid, warp = 64x32
    int g = lane >> 2, tig = lane & 3;

    int arow = tid >> 3;                       // 0..31
    int acol = (tid & 7) * 4;                  // 0..28

    int asrc[8];
    #pragma unroll
    for (int p = 0; p < 8; p++) {
        int r = mb + arow + p * 32;
        if (MODE == 1) {
            int win = r >> 8, t = r & 255;
            int bb = win >> 8, wi = win & 255;
            int wr = wi >> 4,  wc = wi & 15;
            int rr = t  >> 4,  cc = t  & 15;
            asrc[p] = bb * 65536 + (wr * 16 + rr) * 256 + (wc * 16 + cc);
        } else {
            asrc[p] = r;
        }
    }

    uint32_t sA = (uint32_t)__cvta_generic_to_shared(Asm);
    uint32_t sB = (uint32_t)__cvta_generic_to_shared(Bsm);

    auto issue = [&](int it, int buf) {
        int k0 = it * BK;
        uint32_t da = sA + (uint32_t)(buf * ASZ) * 4u;
        uint32_t db = sB + (uint32_t)(buf * BSZ) * 4u;
        #pragma unroll
        for (int p = 0; p < 8; p++)
            cp16(da + (uint32_t)((arow + p * 32) * AS + acol) * 4u,
                 A + (size_t)asrc[p] * K + k0 + acol);
        #pragma unroll
        for (int p = 0; p < 2; p++) {
            int r = arow + p * 32;
            cp16(db + (uint32_t)(r * AS + acol) * 4u,
                 W + (size_t)(nb + r) * K + k0 + acol);
        }
    };

    float acc[4][4][4];
    #pragma unroll
    for (int mt = 0; mt < 4; mt++)
        #pragma unroll
        for (int nt = 0; nt < 4; nt++)
            #pragma unroll
            for (int i = 0; i < 4; i++) acc[mt][nt][i] = 0.f;

    issue(0, 0); CP_COMMIT();

    for (int it = 0; it < NIT; it++) {
        int buf = it & 1;
        if (it + 1 < NIT) { issue(it + 1, buf ^ 1); CP_COMMIT(); CP_WAIT1(); }
        else             { CP_WAIT0(); }
        __syncthreads();

        const float* as = Asm + buf * ASZ;
        const float* bs = Bsm + buf * BSZ;
        #pragma unroll
        for (int ks = 0; ks < 4; ks++) {
            int kk = ks * 8;
            float a[4][4], b[4][2];
            #pragma unroll
            for (int mt = 0; mt < 4; mt++) {
                int r0 = wm * 64 + mt * 16;
                a[mt][0] = as[(r0 + g) * AS + kk + tig];
                a[mt][1] = as[(r0 + g + 8) * AS + kk + tig];
                a[mt][2] = as[(r0 + g) * AS + kk + tig + 4];
                a[mt][3] = as[(r0 + g + 8) * AS + kk + tig + 4];
            }
            #pragma unroll
            for (int nt = 0; nt < 4; nt++) {
                int c0 = wn * 32 + nt * 8;
                b[nt][0] = bs[(c0 + g) * AS + kk + tig];
                b[nt][1] = bs[(c0 + g) * AS + kk + tig + 4];
            }
            #pragma unroll
            for (int mt = 0; mt < 4; mt++)
                #pragma unroll
                for (int nt = 0; nt < 4; nt++)
                    mma_tf32(acc[mt][nt], a[mt], b[nt]);
        }
        __syncthreads();
    }

    #pragma unroll
    for (int mt = 0; mt < 4; mt++) {
        #pragma unroll
        for (int half = 0; half < 2; half++) {
            int row = mb + wm * 64 + mt * 16 + g + half * 8;
            int nat = row;
            if (MODE == 2) {
                int win = row >> 6, t = row & 63;
                int bI = win >> 8, wi = win & 255;
                int wr = wi >> 4,  wc = wi & 15;
                int rr = t  >> 3,  cc = t  & 7;
                nat = bI * 16384 + (wr * 8 + rr) * 128 + (wc * 8 + cc);
            }
            #pragma unroll
            for (int nt = 0; nt < 4; nt++) {
                int col = nb + wn * 32 + nt * 8 + tig * 2;
                float2 o;
                o.x = acc[mt][nt][half * 2 + 0] + bias[col];
                o.y = acc[mt][nt][half * 2 + 1] + bias[col + 1];
                if (MODE == 2) {
                    float2 s = *(const float2*)(add + (size_t)nat * DIM + col);
                    o.x += s.x; o.y += s.y;
                    *(float2*)(C + (size_t)nat * DIM + col) = o;
                } else if (MODE == 3) {
                    o.x = 0.5f * o.x * (1.0f + erff(o.x * 0.70710678118654752f));
                    o.y = 0.5f * o.y * (1.0f + erff(o.y * 0.70710678118654752f));
                    *(float2*)(C + (size_t)row * N + col) = o;
                } else if (MODE == 4) {
                    float2 s = *(const float2*)(add + (size_t)row * N + col);
                    o.x += s.x; o.y += s.y;
                    *(float2*)(C + (size_t)row * N + col) = o;
                } else {
                    *(float2*)(C + (size_t)row * N + col) = o;
                }
            }
        }
    }
}

// ---------------- Attention v3: register-resident S + k-pair-packed smem ------
// 128 threads = 4 warps per (window, head). Warp w owns q-rows 16w..16w+15 and
// all 256 KV columns. Smem layout packs fragment pairs {k+t, k+t+4} adjacently:
// p(c) = (c & ~7) + (c&3)*2 + ((c&4)>>2), so every fragment is one LDS.64.
// Row strides 40 / 264 (== 8 mod 32) -> conflict-free half-warp LDS.64.
#define QS 40       // sQ/sK row stride
#define PS 264      // sVT row stride
#define OFF_K  2560
#define OFF_VT 12800
#define OFF_B  21248
#define ATTN_SMEM_FLOATS 21784

__global__ __launch_bounds__(128) void attn_kernel(const float* __restrict__ rel_bias)
{
    extern __shared__ float sm[];
    float* sQ  = sm;             // 64 x 40, packed
    float* sK  = sm + OFF_K;     // 256 x 40, packed
    float* sVT = sm + OFF_VT;    // 32 x 264, packed along kv index
    float* sB  = sm + OFF_B;     // 529

    int win = blockIdx.x, h = blockIdx.y;
    int tid = threadIdx.x;

    for (int r = tid; r < 529; r += 128) sB[r] = rel_bias[r * HEADS + h];

    // Q: 64 rows x 32, pack columns
    const float* qb = g_q + (size_t)win * 64 * DIM + h * HD;
    #pragma unroll
    for (int it = 0; it < 4; it++) {
        int idx = tid + it * 128;          // 0..511
        int i = idx >> 3, qd = (idx & 7) * 4;
        float4 v = *(const float4*)(qb + (size_t)i * DIM + qd);
        int base = (qd & ~7) + ((qd & 4) >> 2);
        float* s = &sQ[i * QS + base];
        s[0] = v.x; s[2] = v.y; s[4] = v.z; s[6] = v.w;
    }
    // K, V: 256 rows x 32 each
    const float* kb = g_kv + (size_t)win * 256 * (2 * DIM) + h * HD;
    const float* vb = kb + DIM;
    #pragma unroll
    for (int it = 0; it < 16; it++) {
        int idx = tid + it * 128;          // 0..2047
        int j = idx >> 3, qd = (idx & 7) * 4;
        float4 k4 = *(const float4*)(kb + (size_t)j * (2 * DIM) + qd);
        int base = (qd & ~7) + ((qd & 4) >> 2);
        float* s = &sK[j * QS + base];
        s[0] = k4.x; s[2] = k4.y; s[4] = k4.z; s[6] = k4.w;
        float4 v4 = *(const float4*)(vb + (size_t)j * (2 * DIM) + qd);
        int pj = (j & ~7) + (j & 3) * 2 + ((j & 4) >> 2);
        sVT[(qd + 0) * PS + pj] = v4.x;
        sVT[(qd + 1) * PS + pj] = v4.y;
        sVT[(qd + 2) * PS + pj] = v4.z;
        sVT[(qd + 3) * PS + pj] = v4.w;
    }
    __syncthreads();

    int warp = tid >> 5, lane = tid & 31;
    int g = lane >> 2, tig = lane & 3;
    int r0 = warp * 16;

    // ---- QK: S = Q @ K^T, full 16x256 in registers
    float acc[32][4];
    #pragma unroll
    for (int nt = 0; nt < 32; nt++)
        #pragma unroll
        for (int i = 0; i < 4; i++) acc[nt][i] = 0.f;

    #pragma unroll
    for (int ks = 0; ks < 4; ks++) {
        int kk = ks * 8;
        float2 alo = *(const float2*)&sQ[(r0 + g) * QS + kk + tig * 2];
        float2 ahi = *(const float2*)&sQ[(r0 + g + 8) * QS + kk + tig * 2];
        float a[4] = {alo.x, ahi.x, alo.y, ahi.y};
        #pragma unroll
        for (int nt = 0; nt < 32; nt++) {
            float2 bb = *(const float2*)&sK[(nt * 8 + g) * QS + kk + tig * 2];
            float b[2] = {bb.x, bb.y};
            mma_tf32(acc[nt], a, b);
        }
    }

    // ---- scale + bias: ridx = 23*(i>>3) + (i&7) - 23*(j>>4) - (j&15) + 360
    int i_lo = r0 + g, i_hi = i_lo + 8;
    int xlo = (i_lo >> 3) * 23 + (i_lo & 7) + 360;
    int xhi = (i_hi >> 3) * 23 + (i_hi & 7) + 360;
    #pragma unroll
    for (int nt = 0; nt < 32; nt++) {
        int j0 = nt * 8 + tig * 2, j1 = j0 + 1;
        int y0 = 23 * (j0 >> 4) + (j0 & 15);
        int y1 = 23 * (j1 >> 4) + (j1 & 15);
        acc[nt][0] = acc[nt][0] * SCALE + sB[xlo - y0];
        acc[nt][1] = acc[nt][1] * SCALE + sB[xlo - y1];
        acc[nt][2] = acc[nt][2] * SCALE + sB[xhi - y0];
        acc[nt][3] = acc[nt][3] * SCALE + sB[xhi - y1];
    }

    // ---- softmax (rows i_lo, i_hi), quad-shuffle reductions only
    float mlo = -1e30f, mhi = -1e30f;
    #pragma unroll
    for (int nt = 0; nt < 32; nt++) {
        mlo = fmaxf(mlo, fmaxf(acc[nt][0], acc[nt][1]));
        mhi = fmaxf(mhi, fmaxf(acc[nt][2], acc[nt][3]));
    }
    #pragma unroll
    for (int off = 1; off < 4; off <<= 1) {
        mlo = fmaxf(mlo, __shfl_xor_sync(0xffffffffu, mlo, off));
        mhi = fmaxf(mhi, __shfl_xor_sync(0xffffffffu, mhi, off));
    }
    float slo = 0.f, shi = 0.f;
    #pragma unroll
    for (int nt = 0; nt < 32; nt++) {
        acc[nt][0] = __expf(acc[nt][0] - mlo); slo += acc[nt][0];
        acc[nt][1] = __expf(acc[nt][1] - mlo); slo += acc[nt][1];
        acc[nt][2] = __expf(acc[nt][2] - mhi); shi += acc[nt][2];
        acc[nt][3] = __expf(acc[nt][3] - mhi); shi += acc[nt][3];
    }
    #pragma unroll
    for (int off = 1; off < 4; off <<= 1) {
        slo += __shfl_xor_sync(0xffffffffu, slo, off);
        shi += __shfl_xor_sync(0xffffffffu, shi, off);
    }
    float invlo = 1.0f / slo, invhi = 1.0f / shi;
    #pragma unroll
    for (int nt = 0; nt < 32; nt++) {
        acc[nt][0] *= invlo; acc[nt][1] *= invlo;
        acc[nt][2] *= invhi; acc[nt][3] *= invhi;
    }

    // ---- PV: O = P @ V. P accumulator -> A fragments via in-quad shuffle
    // transpose: c-layout cols {2t, 2t+1} -> a-layout cols {t, t+4}.
    float o[4][4];
    #pragma unroll
    for (int nt = 0; nt < 4; nt++)
        #pragma unroll
        for (int i = 0; i < 4; i++) o[nt][i] = 0.f;

    int src_a = (lane & ~3) | (tig >> 1);
    int src_b = src_a + 2;
    bool odd = (tig & 1);

    #pragma unroll
    for (int kc = 0; kc < 32; kc++) {
        float s0 = __shfl_sync(0xffffffffu, acc[kc][0], src_a);
        float s1 = __shfl_sync(0xffffffffu, acc[kc][1], src_a);
        float s2 = __shfl_sync(0xffffffffu, acc[kc][0], src_b);
        float s3 = __shfl_sync(0xffffffffu, acc[kc][1], src_b);
        float t0 = __shfl_sync(0xffffffffu, acc[kc][2], src_a);
        float t1 = __shfl_sync(0xffffffffu, acc[kc][3], src_a);
        float t2 = __shfl_sync(0xffffffffu, acc[kc][2], src_b);
        float t3 = __shfl_sync(0xffffffffu, acc[kc][3], src_b);
        float a[4];
        a[0] = odd ? s1 : s0;   // P[g   ][8kc + tig]
        a[1] = odd ? t1 : t0;   // P[g+8 ][8kc + tig]
        a[2] = odd ? s3 : s2;   // P[g   ][8kc + tig + 4]
        a[3] = odd ? t3 : t2;   // P[g+8 ][8kc + tig + 4]
        #pragma unroll
        for (int nt = 0; nt < 4; nt++) {
            float2 bb = *(const float2*)&sVT[(nt * 8 + g) * PS + kc * 8 + tig * 2];
            float b[2] = {bb.x, bb.y};
            mma_tf32(o[nt], a, b);
        }
    }

    // ---- store O (fp32)
    float* ob = g_ao + (size_t)win * 64 * DIM + h * HD;
    #pragma unroll
    for (int nt = 0; nt < 4; nt++) {
        int col = nt * 8 + tig * 2;
        *(float2*)(ob + (size_t)i_lo * DIM + col) = make_float2(o[nt][0], o[nt][1]);
        *(float2*)(ob + (size_t)i_hi * DIM + col) = make_float2(o[nt][2], o[nt][3]);
    }
}

// ---------------- launch ----------------
extern "C" void kernel_launch(void* const* d_in, const int* in_sizes, int n_in,
                              void* d_out, int out_size)
{
    const float* x     = (const float*)d_in[0];
    const float* x2    = (const float*)d_in[1];
    const float* n1w   = (const float*)d_in[2];
    const float* n1b   = (const float*)d_in[3];
    const float* qkvw  = (const float*)d_in[4];
    const float* qkvb  = (const float*)d_in[5];
    const float* qkv2w = (const float*)d_in[6];
    const float* qkv2b = (const float*)d_in[7];
    const float* relb  = (const float*)d_in[8];
    const float* projw = (const float*)d_in[9];
    const float* projb = (const float*)d_in[10];
    const float* n2w   = (const float*)d_in[11];
    const float* n2b   = (const float*)d_in[12];
    const float* fc1w  = (const float*)d_in[13];
    const float* fc1b  = (const float*)d_in[14];
    const float* fc2w  = (const float*)d_in[15];
    const float* fc2b  = (const float*)d_in[16];
    float* out = (float*)d_out;

    float *p_xn, *p_q, *p_kv, *p_ao, *p_x1, *p_ln2, *p_h;
    cudaGetSymbolAddress((void**)&p_xn,  g_xn);
    cudaGetSymbolAddress((void**)&p_q,   g_q);
    cudaGetSymbolAddress((void**)&p_kv,  g_kv);
    cudaGetSymbolAddress((void**)&p_ao,  g_ao);
    cudaGetSymbolAddress((void**)&p_x1,  g_x1);
    cudaGetSymbolAddress((void**)&p_ln2, g_ln2);
    cudaGetSymbolAddress((void**)&p_h,   g_h);

    const int attn_smem = ATTN_SMEM_FLOATS * (int)sizeof(float);
    cudaFuncSetAttribute(attn_kernel, cudaFuncAttributeMaxDynamicSharedMemorySize, attn_smem);
    cudaFuncSetAttribute(gemm_tf32<0, 192, 192>, cudaFuncAttributeMaxDynamicSharedMemorySize, GEMM_SMEM);
    cudaFuncSetAttribute(gemm_tf32<1, 384, 192>, cudaFuncAttributeMaxDynamicSharedMemorySize, GEMM_SMEM);
    cudaFuncSetAttribute(gemm_tf32<2, 192, 192>, cudaFuncAttributeMaxDynamicSharedMemorySize, GEMM_SMEM);
    cudaFuncSetAttribute(gemm_tf32<3, 768, 192>, cudaFuncAttributeMaxDynamicSharedMemorySize, GEMM_SMEM);
    cudaFuncSetAttribute(gemm_tf32<4, 192, 768>, cudaFuncAttributeMaxDynamicSharedMemorySize, GEMM_SMEM);

    // 1. LN1 + window partition
    ln_kernel<0><<<NQTOK, 192>>>(x, n1w, n1b, p_xn);
    // 2. q projection (window order)
    gemm_tf32<0, 192, 192><<<dim3(256, 3), 256, GEMM_SMEM>>>(p_xn, qkvw, qkvb, p_q, nullptr);
    // 3. kv projection (gather x2 through 16x16 window partition)
    gemm_tf32<1, 384, 192><<<dim3(1024, 6), 256, GEMM_SMEM>>>(x2, qkv2w, qkv2b, p_kv, nullptr);
    // 4. windowed cross attention (register-resident tensor cores)
    attn_kernel<<<dim3(NWIN, HEADS), 128, attn_smem>>>(relb);
    // 5. output projection + shortcut + window reverse -> natural order
    gemm_tf32<2, 192, 192><<<dim3(256, 3), 256, GEMM_SMEM>>>(p_ao, projw, projb, p_x1, x);
    // 6. LN2
    ln_kernel<1><<<NQTOK, 192>>>(p_x1, n2w, n2b, p_ln2);
    // 7. fc1 + gelu
    gemm_tf32<3, 768, 192><<<dim3(256, 12), 256, GEMM_SMEM>>>(p_ln2, fc1w, fc1b, p_h, nullptr);
    // 8. fc2 + residual -> output
    gemm_tf32<4, 192, 768><<<dim3(256, 3), 256, GEMM_SMEM>>>(p_h, fc2w, fc2b, out, p_x1);
}

// round 9
// speedup vs baseline: 1.1735x; 1.1735x over previous
#include <cuda_runtime.h>
#include <math.h>
#include <stdint.h>

#define DIM   192
#define HEADS 6
#define HD    32
#define NWIN  1024          // 4 * 16 * 16
#define NQTOK 65536         // 1024 * 64  (== B*L)
#define NKVTOK 262144       // 1024 * 256
#define SCALE 0.17677669529663687f   // 32^-0.5

// ---------------- scratch (device globals; no runtime allocation) ----------------
__device__ float g_xn [(size_t)NQTOK * DIM];        // LN1 output, window order
__device__ float g_q  [(size_t)NQTOK * DIM];        // q projection, window order
__device__ float g_kv [(size_t)NKVTOK * 2 * DIM];   // k | v, window order
__device__ float g_ao [(size_t)NQTOK * DIM];        // attention output, window order
__device__ float g_x1 [(size_t)NQTOK * DIM];        // x after first residual
__device__ float g_ln2[(size_t)NQTOK * DIM];        // LN2 output
__device__ float g_h  [(size_t)NQTOK * 4 * DIM];    // gelu(fc1) output

// ---------------- helpers ----------------
__device__ __forceinline__ void mma_tf32(float* d, const float* a, const float* b) {
    asm volatile(
        "mma.sync.aligned.m16n8k8.row.col.f32.tf32.tf32.f32 "
        "{%0,%1,%2,%3}, {%4,%5,%6,%7}, {%8,%9}, {%0,%1,%2,%3};\n"
        : "+f"(d[0]), "+f"(d[1]), "+f"(d[2]), "+f"(d[3])
        : "r"(__float_as_uint(a[0])), "r"(__float_as_uint(a[1])),
          "r"(__float_as_uint(a[2])), "r"(__float_as_uint(a[3])),
          "r"(__float_as_uint(b[0])), "r"(__float_as_uint(b[1])));
}

__device__ __forceinline__ void mma_bf16(float* d, const uint32_t* a, const uint32_t* b) {
    asm volatile(
        "mma.sync.aligned.m16n8k16.row.col.f32.bf16.bf16.f32 "
        "{%0,%1,%2,%3}, {%4,%5,%6,%7}, {%8,%9}, {%0,%1,%2,%3};\n"
        : "+f"(d[0]), "+f"(d[1]), "+f"(d[2]), "+f"(d[3])
        : "r"(a[0]), "r"(a[1]), "r"(a[2]), "r"(a[3]),
          "r"(b[0]), "r"(b[1]));
}

// pack {lo = v.x (k), hi = v.y (k+1)} -- first cvt source goes to the upper half
__device__ __forceinline__ uint32_t packbf(float2 v) {
    uint32_t r;
    asm("cvt.rn.bf16x2.f32 %0, %1, %2;" : "=r"(r) : "f"(v.y), "f"(v.x));
    return r;
}

__device__ __forceinline__ void cp16(uint32_t dst, const void* src) {
    asm volatile("cp.async.cg.shared.global [%0], [%1], 16;\n" :: "r"(dst), "l"(src));
}
#define CP_COMMIT() asm volatile("cp.async.commit_group;\n")
#define CP_WAIT1()  asm volatile("cp.async.wait_group 1;\n")
#define CP_WAIT0()  asm volatile("cp.async.wait_group 0;\n")

// ---------------- LayerNorm (one token per block, 192 threads) ----------------
template<int MODE>
__global__ __launch_bounds__(192) void ln_kernel(
    const float* __restrict__ x, const float* __restrict__ w,
    const float* __restrict__ b, float* __restrict__ out)
{
    int tok = blockIdx.x;
    int tid = threadIdx.x;
    int in_row, out_row;
    if (MODE == 0) {
        int win = tok >> 6, t = tok & 63;
        int bb = win >> 8, wi = win & 255;
        int wr = wi >> 4,  wc = wi & 15;
        int r  = t  >> 3,  c  = t  & 7;
        in_row  = bb * 16384 + (wr * 8 + r) * 128 + (wc * 8 + c);
        out_row = tok;
    } else {
        in_row = out_row = tok;
    }
    float v = x[(size_t)in_row * DIM + tid];
    float s1 = v, s2 = v * v;
    #pragma unroll
    for (int off = 16; off; off >>= 1) {
        s1 += __shfl_xor_sync(0xffffffffu, s1, off);
        s2 += __shfl_xor_sync(0xffffffffu, s2, off);
    }
    __shared__ float red[12];
    int warp = tid >> 5, lane = tid & 31;
    if (lane == 0) { red[warp] = s1; red[6 + warp] = s2; }
    __syncthreads();
    if (tid == 0) {
        float a = 0.f, c2 = 0.f;
        #pragma unroll
        for (int i = 0; i < 6; i++) { a += red[i]; c2 += red[6 + i]; }
        red[0] = a; red[6] = c2;
    }
    __syncthreads();
    float mean = red[0] * (1.0f / 192.0f);
    float var  = red[6] * (1.0f / 192.0f) - mean * mean;
    float rstd = rsqrtf(var + 1e-5f);
    out[(size_t)out_row * DIM + tid] = (v - mean) * rstd * w[tid] + b[tid];
}

// ---------------- BF16 GEMM, BM=256, cp.async double-buffered ----------------
// C = A @ W^T + bias, fp32 in gmem/smem, bf16 conversion at fragment load,
// fp32 accumulate. W is (N, K) row-major.
// MODE 0: plain.  MODE 1: gather A rows through 16x16 window partition of x2.
// MODE 2: + add[nat_row], store window-reversed.  MODE 3: exact gelu.
// MODE 4: + add[row].
#define GEMM_AS  40
#define GEMM_ASZ (256 * GEMM_AS)
#define GEMM_BSZ (64 * GEMM_AS)
#define GEMM_SMEM ((2 * GEMM_ASZ + 2 * GEMM_BSZ) * 4)

template<int MODE, int N, int K>
__global__ __launch_bounds__(256) void gemm_bf16(
    const float* __restrict__ A, const float* __restrict__ W,
    const float* __restrict__ bias, float* __restrict__ C,
    const float* __restrict__ add)
{
    constexpr int BM = 256, BN = 64, BK = 32, AS = GEMM_AS;
    constexpr int ASZ = GEMM_ASZ, BSZ = GEMM_BSZ;
    constexpr int NIT = K / BK;
    extern __shared__ float smg[];
    float* Asm = smg;               // 2 * ASZ
    float* Bsm = smg + 2 * ASZ;     // 2 * BSZ

    int tid = threadIdx.x;
    int mb = blockIdx.x * BM, nb = blockIdx.y * BN;
    int warp = tid >> 5, lane = tid & 31;
    int wm = warp & 3, wn = warp >> 2;         // 4m x 2n warp grid, warp = 64x32
    int g = lane >> 2, tig = lane & 3;

    int arow = tid >> 3;                       // 0..31
    int acol = (tid & 7) * 4;                  // 0..28

    int asrc[8];
    #pragma unroll
    for (int p = 0; p < 8; p++) {
        int r = mb + arow + p * 32;
        if (MODE == 1) {
            int win = r >> 8, t = r & 255;
            int bb = win >> 8, wi = win & 255;
            int wr = wi >> 4,  wc = wi & 15;
            int rr = t  >> 4,  cc = t  & 15;
            asrc[p] = bb * 65536 + (wr * 16 + rr) * 256 + (wc * 16 + cc);
        } else {
            asrc[p] = r;
        }
    }

    uint32_t sA = (uint32_t)__cvta_generic_to_shared(Asm);
    uint32_t sB = (uint32_t)__cvta_generic_to_shared(Bsm);

    auto issue = [&](int it, int buf) {
        int k0 = it * BK;
        uint32_t da = sA + (uint32_t)(buf * ASZ) * 4u;
        uint32_t db = sB + (uint32_t)(buf * BSZ) * 4u;
        #pragma unroll
        for (int p = 0; p < 8; p++)
            cp16(da + (uint32_t)((arow + p * 32) * AS + acol) * 4u,
                 A + (size_t)asrc[p] * K + k0 + acol);
        #pragma unroll
        for (int p = 0; p < 2; p++) {
            int r = arow + p * 32;
            cp16(db + (uint32_t)(r * AS + acol) * 4u,
                 W + (size_t)(nb + r) * K + k0 + acol);
        }
    };

    float acc[4][4][4];
    #pragma unroll
    for (int mt = 0; mt < 4; mt++)
        #pragma unroll
        for (int nt = 0; nt < 4; nt++)
            #pragma unroll
            for (int i = 0; i < 4; i++) acc[mt][nt][i] = 0.f;

    issue(0, 0); CP_COMMIT();

    for (int it = 0; it < NIT; it++) {
        int buf = it & 1;
        if (it + 1 < NIT) { issue(it + 1, buf ^ 1); CP_COMMIT(); CP_WAIT1(); }
        else             { CP_WAIT0(); }
        __syncthreads();

        const float* as = Asm + buf * ASZ;
        const float* bs = Bsm + buf * BSZ;
        #pragma unroll
        for (int ks = 0; ks < 2; ks++) {
            int kk = ks * 16;
            uint32_t a[4][4], b[4][2];
            #pragma unroll
            for (int mt = 0; mt < 4; mt++) {
                int r0 = wm * 64 + mt * 16;
                const float* pr = as + (r0 + g) * AS + kk + tig * 2;
                a[mt][0] = packbf(*(const float2*)pr);
                a[mt][1] = packbf(*(const float2*)(pr + 8 * AS));
                a[mt][2] = packbf(*(const float2*)(pr + 8));
                a[mt][3] = packbf(*(const float2*)(pr + 8 * AS + 8));
            }
            #pragma unroll
            for (int nt = 0; nt < 4; nt++) {
                const float* pc = bs + (wn * 32 + nt * 8 + g) * AS + kk + tig * 2;
                b[nt][0] = packbf(*(const float2*)pc);
                b[nt][1] = packbf(*(const float2*)(pc + 8));
            }
            #pragma unroll
            for (int mt = 0; mt < 4; mt++)
                #pragma unroll
                for (int nt = 0; nt < 4; nt++)
                    mma_bf16(acc[mt][nt], a[mt], b[nt]);
        }
        __syncthreads();
    }

    #pragma unroll
    for (int mt = 0; mt < 4; mt++) {
        #pragma unroll
        for (int half = 0; half < 2; half++) {
            int row = mb + wm * 64 + mt * 16 + g + half * 8;
            int nat = row;
            if (MODE == 2) {
                int win = row >> 6, t = row & 63;
                int bI = win >> 8, wi = win & 255;
                int wr = wi >> 4,  wc = wi & 15;
                int rr = t  >> 3,  cc = t  & 7;
                nat = bI * 16384 + (wr * 8 + rr) * 128 + (wc * 8 + cc);
            }
            #pragma unroll
            for (int nt = 0; nt < 4; nt++) {
                int col = nb + wn * 32 + nt * 8 + tig * 2;
                float2 o;
                o.x = acc[mt][nt][half * 2 + 0] + bias[col];
                o.y = acc[mt][nt][half * 2 + 1] + bias[col + 1];
                if (MODE == 2) {
                    float2 s = *(const float2*)(add + (size_t)nat * DIM + col);
                    o.x += s.x; o.y += s.y;
                    *(float2*)(C + (size_t)nat * DIM + col) = o;
                } else if (MODE == 3) {
                    o.x = 0.5f * o.x * (1.0f + erff(o.x * 0.70710678118654752f));
                    o.y = 0.5f * o.y * (1.0f + erff(o.y * 0.70710678118654752f));
                    *(float2*)(C + (size_t)row * N + col) = o;
                } else if (MODE == 4) {
                    float2 s = *(const float2*)(add + (size_t)row * N + col);
                    o.x += s.x; o.y += s.y;
                    *(float2*)(C + (size_t)row * N + col) = o;
                } else {
                    *(float2*)(C + (size_t)row * N + col) = o;
                }
            }
        }
    }
}

// ---------------- Attention (R7 structure + corrected bias fold) ---------------
// 128 threads = 4 warps per (window, head). Warp w owns q-rows 16w..16w+15 and
// ALL 256 KV columns: S tile (16x256) lives in MMA accumulators, softmax is
// quad-shuffle only, P -> A-fragments via in-quad shuffle transpose, PV direct.
#define QS 36      // sQ/sK row stride
#define PS 260     // sVT row stride
#define OFF_K  2304
#define OFF_VT 11520
#define OFF_B  19840
#define ATTN_SMEM_FLOATS 20372

__global__ __launch_bounds__(128) void attn_kernel(const float* __restrict__ rel_bias)
{
    extern __shared__ float sm[];
    float* sQ  = sm;             // 64 x 36
    float* sK  = sm + OFF_K;     // 256 x 36
    float* sVT = sm + OFF_VT;    // 32 x 260  (VT[d][j])
    float* sB  = sm + OFF_B;     // 529

    int win = blockIdx.x, h = blockIdx.y;
    int tid = threadIdx.x;

    for (int r = tid; r < 529; r += 128) sB[r] = rel_bias[r * HEADS + h];

    const float* qb = g_q + (size_t)win * 64 * DIM + h * HD;
    #pragma unroll
    for (int it = 0; it < 4; it++) {
        int idx = tid + it * 128;          // 0..511
        int i = idx >> 3, qd = (idx & 7) * 4;
        float4 v = *(const float4*)(qb + (size_t)i * DIM + qd);
        *(float4*)&sQ[i * QS + qd] = v;
    }
    const float* kb = g_kv + (size_t)win * 256 * (2 * DIM) + h * HD;
    const float* vb = kb + DIM;
    #pragma unroll
    for (int it = 0; it < 16; it++) {
        int idx = tid + it * 128;          // 0..2047
        int j = idx >> 3, qd = (idx & 7) * 4;
        float4 kv4 = *(const float4*)(kb + (size_t)j * (2 * DIM) + qd);
        *(float4*)&sK[j * QS + qd] = kv4;
        float4 vv4 = *(const float4*)(vb + (size_t)j * (2 * DIM) + qd);
        sVT[(qd + 0) * PS + j] = vv4.x;
        sVT[(qd + 1) * PS + j] = vv4.y;
        sVT[(qd + 2) * PS + j] = vv4.z;
        sVT[(qd + 3) * PS + j] = vv4.w;
    }
    __syncthreads();

    int warp = tid >> 5, lane = tid & 31;
    int g = lane >> 2, tig = lane & 3;
    int r0 = warp * 16;

    // ---- QK: S = Q @ K^T, full 16x256 in registers
    float acc[32][4];
    #pragma unroll
    for (int nt = 0; nt < 32; nt++)
        #pragma unroll
        for (int i = 0; i < 4; i++) acc[nt][i] = 0.f;

    #pragma unroll
    for (int ks = 0; ks < 4; ks++) {
        int kk = ks * 8;
        float a[4];
        a[0] = sQ[(r0 + g) * QS + kk + tig];
        a[1] = sQ[(r0 + g + 8) * QS + kk + tig];
        a[2] = sQ[(r0 + g) * QS + kk + tig + 4];
        a[3] = sQ[(r0 + g + 8) * QS + kk + tig + 4];
        #pragma unroll
        for (int nt = 0; nt < 32; nt++) {
            float b[2];
            b[0] = sK[(nt * 8 + g) * QS + kk + tig];
            b[1] = sK[(nt * 8 + g) * QS + kk + tig + 4];
            mma_tf32(acc[nt], a, b);
        }
    }

    // ---- scale + bias: ridx = 23*(i>>3) + (i&7) + 360 - 23*(j>>4) - (j&15)
    int i_lo = r0 + g, i_hi = i_lo + 8;
    int xlo = (i_lo >> 3) * 23 + (i_lo & 7) + 360;
    int xhi = (i_hi >> 3) * 23 + (i_hi & 7) + 360;
    #pragma unroll
    for (int nt = 0; nt < 32; nt++) {
        int j0 = nt * 8 + tig * 2, j1 = j0 + 1;
        int y0 = 23 * (j0 >> 4) + (j0 & 15);
        int y1 = 23 * (j1 >> 4) + (j1 & 15);
        acc[nt][0] = acc[nt][0] * SCALE + sB[xlo - y0];
        acc[nt][1] = acc[nt][1] * SCALE + sB[xlo - y1];
        acc[nt][2] = acc[nt][2] * SCALE + sB[xhi - y0];
        acc[nt][3] = acc[nt][3] * SCALE + sB[xhi - y1];
    }

    // ---- softmax (rows i_lo, i_hi), quad-shuffle reductions only
    float mlo = -1e30f, mhi = -1e30f;
    #pragma unroll
    for (int nt = 0; nt < 32; nt++) {
        mlo = fmaxf(mlo, fmaxf(acc[nt][0], acc[nt][1]));
        mhi = fmaxf(mhi, fmaxf(acc[nt][2], acc[nt][3]));
    }
    #pragma unroll
    for (int off = 1; off < 4; off <<= 1) {
        mlo = fmaxf(mlo, __shfl_xor_sync(0xffffffffu, mlo, off));
        mhi = fmaxf(mhi, __shfl_xor_sync(0xffffffffu, mhi, off));
    }
    float slo = 0.f, shi = 0.f;
    #pragma unroll
    for (int nt = 0; nt < 32; nt++) {
        acc[nt][0] = __expf(acc[nt][0] - mlo); slo += acc[nt][0];
        acc[nt][1] = __expf(acc[nt][1] - mlo); slo += acc[nt][1];
        acc[nt][2] = __expf(acc[nt][2] - mhi); shi += acc[nt][2];
        acc[nt][3] = __expf(acc[nt][3] - mhi); shi += acc[nt][3];
    }
    #pragma unroll
    for (int off = 1; off < 4; off <<= 1) {
        slo += __shfl_xor_sync(0xffffffffu, slo, off);
        shi += __shfl_xor_sync(0xffffffffu, shi, off);
    }
    float invlo = 1.0f / slo, invhi = 1.0f / shi;
    #pragma unroll
    for (int nt = 0; nt < 32; nt++) {
        acc[nt][0] *= invlo; acc[nt][1] *= invlo;
        acc[nt][2] *= invhi; acc[nt][3] *= invhi;
    }

    // ---- PV: O = P @ V. P accumulator -> A fragments via in-quad shuffle
    // transpose: c-layout cols {2t, 2t+1} -> a-layout cols {t, t+4}.
    float o[4][4];
    #pragma unroll
    for (int nt = 0; nt < 4; nt++)
        #pragma unroll
        for (int i = 0; i < 4; i++) o[nt][i] = 0.f;

    int src_a = (lane & ~3) | (tig >> 1);
    int src_b = src_a + 2;
    bool odd = (tig & 1);

    #pragma unroll
    for (int kc = 0; kc < 32; kc++) {
        float s0 = __shfl_sync(0xffffffffu, acc[kc][0], src_a);
        float s1 = __shfl_sync(0xffffffffu, acc[kc][1], src_a);
        float s2 = __shfl_sync(0xffffffffu, acc[kc][0], src_b);
        float s3 = __shfl_sync(0xffffffffu, acc[kc][1], src_b);
        float t0 = __shfl_sync(0xffffffffu, acc[kc][2], src_a);
        float t1 = __shfl_sync(0xffffffffu, acc[kc][3], src_a);
        float t2 = __shfl_sync(0xffffffffu, acc[kc][2], src_b);
        float t3 = __shfl_sync(0xffffffffu, acc[kc][3], src_b);
        float a[4];
        a[0] = odd ? s1 : s0;   // P[g   ][8kc + tig]
        a[1] = odd ? t1 : t0;   // P[g+8 ][8kc + tig]
        a[2] = odd ? s3 : s2;   // P[g   ][8kc + tig + 4]
        a[3] = odd ? t3 : t2;   // P[g+8 ][8kc + tig + 4]
        #pragma unroll
        for (int nt = 0; nt < 4; nt++) {
            float b[2];
            b[0] = sVT[(nt * 8 + g) * PS + kc * 8 + tig];
            b[1] = sVT[(nt * 8 + g) * PS + kc * 8 + tig + 4];
            mma_tf32(o[nt], a, b);
        }
    }

    // ---- store O (fp32)
    float* ob = g_ao + (size_t)win * 64 * DIM + h * HD;
    #pragma unroll
    for (int nt = 0; nt < 4; nt++) {
        int col = nt * 8 + tig * 2;
        *(float2*)(ob + (size_t)i_lo * DIM + col) = make_float2(o[nt][0], o[nt][1]);
        *(float2*)(ob + (size_t)i_hi * DIM + col) = make_float2(o[nt][2], o[nt][3]);
    }
}

// ---------------- launch ----------------
extern "C" void kernel_launch(void* const* d_in, const int* in_sizes, int n_in,
                              void* d_out, int out_size)
{
    const float* x     = (const float*)d_in[0];
    const float* x2    = (const float*)d_in[1];
    const float* n1w   = (const float*)d_in[2];
    const float* n1b   = (const float*)d_in[3];
    const float* qkvw  = (const float*)d_in[4];
    const float* qkvb  = (const float*)d_in[5];
    const float* qkv2w = (const float*)d_in[6];
    const float* qkv2b = (const float*)d_in[7];
    const float* relb  = (const float*)d_in[8];
    const float* projw = (const float*)d_in[9];
    const float* projb = (const float*)d_in[10];
    const float* n2w   = (const float*)d_in[11];
    const float* n2b   = (const float*)d_in[12];
    const float* fc1w  = (const float*)d_in[13];
    const float* fc1b  = (const float*)d_in[14];
    const float* fc2w  = (const float*)d_in[15];
    const float* fc2b  = (const float*)d_in[16];
    float* out = (float*)d_out;

    float *p_xn, *p_q, *p_kv, *p_ao, *p_x1, *p_ln2, *p_h;
    cudaGetSymbolAddress((void**)&p_xn,  g_xn);
    cudaGetSymbolAddress((void**)&p_q,   g_q);
    cudaGetSymbolAddress((void**)&p_kv,  g_kv);
    cudaGetSymbolAddress((void**)&p_ao,  g_ao);
    cudaGetSymbolAddress((void**)&p_x1,  g_x1);
    cudaGetSymbolAddress((void**)&p_ln2, g_ln2);
    cudaGetSymbolAddress((void**)&p_h,   g_h);

    const int attn_smem = ATTN_SMEM_FLOATS * (int)sizeof(float);
    cudaFuncSetAttribute(attn_kernel, cudaFuncAttributeMaxDynamicSharedMemorySize, attn_smem);
    cudaFuncSetAttribute(gemm_bf16<0, 192, 192>, cudaFuncAttributeMaxDynamicSharedMemorySize, GEMM_SMEM);
    cudaFuncSetAttribute(gemm_bf16<1, 384, 192>, cudaFuncAttributeMaxDynamicSharedMemorySize, GEMM_SMEM);
    cudaFuncSetAttribute(gemm_bf16<2, 192, 192>, cudaFuncAttributeMaxDynamicSharedMemorySize, GEMM_SMEM);
    cudaFuncSetAttribute(gemm_bf16<3, 768, 192>, cudaFuncAttributeMaxDynamicSharedMemorySize, GEMM_SMEM);
    cudaFuncSetAttribute(gemm_bf16<4, 192, 768>, cudaFuncAttributeMaxDynamicSharedMemorySize, GEMM_SMEM);

    // 1. LN1 + window partition
    ln_kernel<0><<<NQTOK, 192>>>(x, n1w, n1b, p_xn);
    // 2. q projection (window order)
    gemm_bf16<0, 192, 192><<<dim3(256, 3), 256, GEMM_SMEM>>>(p_xn, qkvw, qkvb, p_q, nullptr);
    // 3. kv projection (gather x2 through 16x16 window partition)
    gemm_bf16<1, 384, 192><<<dim3(1024, 6), 256, GEMM_SMEM>>>(x2, qkv2w, qkv2b, p_kv, nullptr);
    // 4. windowed cross attention (register-resident tensor cores)
    attn_kernel<<<dim3(NWIN, HEADS), 128, attn_smem>>>(relb);
    // 5. output projection + shortcut + window reverse -> natural order
    gemm_bf16<2, 192, 192><<<dim3(256, 3), 256, GEMM_SMEM>>>(p_ao, projw, projb, p_x1, x);
    // 6. LN2
    ln_kernel<1><<<NQTOK, 192>>>(p_x1, n2w, n2b, p_ln2);
    // 7. fc1 + gelu
    gemm_bf16<3, 768, 192><<<dim3(256, 12), 256, GEMM_SMEM>>>(p_ln2, fc1w, fc1b, p_h, nullptr);
    // 8. fc2 + residual -> output
    gemm_bf16<4, 192, 768><<<dim3(256, 3), 256, GEMM_SMEM>>>(p_h, fc2w, fc2b, out, p_x1);
}

// round 10
// speedup vs baseline: 1.3465x; 1.1474x over previous
#include <cuda_runtime.h>
#include <cuda_bf16.h>
#include <math.h>
#include <stdint.h>

#define DIM   192
#define HEADS 6
#define HD    32
#define NWIN  1024          // 4 * 16 * 16
#define NQTOK 65536         // 1024 * 64  (== B*L)
#define NKVTOK 262144       // 1024 * 256
#define SCALE 0.17677669529663687f   // 32^-0.5

// ---------------- scratch (device globals; no runtime allocation) ----------------
__device__ __nv_bfloat16 g_xn [(size_t)NQTOK * DIM];      // LN1 out, window order
__device__ __nv_bfloat16 g_q  [(size_t)NQTOK * DIM];      // q projection
__device__ __nv_bfloat16 g_kv [(size_t)NKVTOK * 2 * DIM]; // k | v, window order
__device__ __nv_bfloat16 g_ao [(size_t)NQTOK * DIM];      // attention output
__device__ float         g_x1 [(size_t)NQTOK * DIM];      // x after first residual (fp32)
__device__ __nv_bfloat16 g_ln2[(size_t)NQTOK * DIM];      // LN2 output
__device__ __nv_bfloat16 g_h  [(size_t)NQTOK * 4 * DIM];  // gelu(fc1) output
// bf16 weights (pre-converted once per launch)
__device__ __nv_bfloat16 g_wq [192 * 192];
__device__ __nv_bfloat16 g_wkv[384 * 192];
__device__ __nv_bfloat16 g_wp [192 * 192];
__device__ __nv_bfloat16 g_w1 [768 * 192];
__device__ __nv_bfloat16 g_w2 [192 * 768];

// ---------------- helpers ----------------
__device__ __forceinline__ void mma_bf16(float* d, const uint32_t* a, const uint32_t* b) {
    asm volatile(
        "mma.sync.aligned.m16n8k16.row.col.f32.bf16.bf16.f32 "
        "{%0,%1,%2,%3}, {%4,%5,%6,%7}, {%8,%9}, {%0,%1,%2,%3};\n"
        : "+f"(d[0]), "+f"(d[1]), "+f"(d[2]), "+f"(d[3])
        : "r"(a[0]), "r"(a[1]), "r"(a[2]), "r"(a[3]),
          "r"(b[0]), "r"(b[1]));
}
// pack: lo half = x (first k), hi half = y
__device__ __forceinline__ uint32_t packbf(float x, float y) {
    uint32_t r;
    asm("cvt.rn.bf16x2.f32 %0, %1, %2;" : "=r"(r) : "f"(y), "f"(x));
    return r;
}
__device__ __forceinline__ void cp16(uint32_t dst, const void* src) {
    asm volatile("cp.async.cg.shared.global [%0], [%1], 16;\n" :: "r"(dst), "l"(src));
}
#define CP_COMMIT() asm volatile("cp.async.commit_group;\n")
#define CP_WAIT1()  asm volatile("cp.async.wait_group 1;\n")
#define CP_WAIT0()  asm volatile("cp.async.wait_group 0;\n")

// ---------------- weight fp32 -> bf16 (n multiple of 4) ----------------
__global__ __launch_bounds__(256) void cvt_w(const float* __restrict__ s,
                                             __nv_bfloat16* __restrict__ d, int n4)
{
    int i = blockIdx.x * 256 + threadIdx.x;
    if (i < n4) {
        float4 v = *(const float4*)(s + (size_t)i * 4);
        uint2 o;
        o.x = packbf(v.x, v.y);
        o.y = packbf(v.z, v.w);
        *(uint2*)((uint32_t*)d + (size_t)i * 2) = o;
    }
}

// ---------------- LayerNorm (one token per block, 192 threads, bf16 out) -------
template<int MODE>
__global__ __launch_bounds__(192) void ln_kernel(
    const float* __restrict__ x, const float* __restrict__ w,
    const float* __restrict__ b, __nv_bfloat16* __restrict__ out)
{
    int tok = blockIdx.x;
    int tid = threadIdx.x;
    int in_row, out_row;
    if (MODE == 0) {
        int win = tok >> 6, t = tok & 63;
        int bb = win >> 8, wi = win & 255;
        int wr = wi >> 4,  wc = wi & 15;
        int r  = t  >> 3,  c  = t  & 7;
        in_row  = bb * 16384 + (wr * 8 + r) * 128 + (wc * 8 + c);
        out_row = tok;
    } else {
        in_row = out_row = tok;
    }
    float v = x[(size_t)in_row * DIM + tid];
    float s1 = v, s2 = v * v;
    #pragma unroll
    for (int off = 16; off; off >>= 1) {
        s1 += __shfl_xor_sync(0xffffffffu, s1, off);
        s2 += __shfl_xor_sync(0xffffffffu, s2, off);
    }
    __shared__ float red[12];
    int warp = tid >> 5, lane = tid & 31;
    if (lane == 0) { red[warp] = s1; red[6 + warp] = s2; }
    __syncthreads();
    if (tid == 0) {
        float a = 0.f, c2 = 0.f;
        #pragma unroll
        for (int i = 0; i < 6; i++) { a += red[i]; c2 += red[6 + i]; }
        red[0] = a; red[6] = c2;
    }
    __syncthreads();
    float mean = red[0] * (1.0f / 192.0f);
    float var  = red[6] * (1.0f / 192.0f) - mean * mean;
    float rstd = rsqrtf(var + 1e-5f);
    out[(size_t)out_row * DIM + tid] =
        __float2bfloat16((v - mean) * rstd * w[tid] + b[tid]);
}

// ---------------- BF16 GEMM, BM=256, cp.async double-buffered ----------------
// C = A @ W^T + bias.  W bf16 (N, K) row-major. A bf16 (ABF) or fp32 gather.
// MODE 0: plain -> bf16.  MODE 1: gather x2 (fp32) through 16x16 windows -> bf16.
// MODE 2: + add[nat_row] -> fp32, window-reversed.  MODE 3: gelu -> bf16.
// MODE 4: + add[row] -> fp32.
#define BAS 20                          // u32 row stride, bf16 A / B tiles
#define FAS 40                          // float row stride, fp32 A tiles
#define BSZ32 (64 * BAS)
#define SM_BF ((2 * 256 * BAS + 2 * BSZ32) * 4)
#define SM_FP ((2 * 256 * FAS + 2 * BSZ32) * 4)

template<int MODE, int N, int K, bool ABF>
__global__ __launch_bounds__(256) void gemm_bf16(
    const void* __restrict__ Av, const __nv_bfloat16* __restrict__ W,
    const float* __restrict__ bias, void* __restrict__ Cv,
    const float* __restrict__ add)
{
    constexpr int BM = 256, BN = 64;
    constexpr int ASZ = ABF ? 256 * BAS : 256 * FAS;   // 4-byte units
    constexpr int NIT = K / 32;
    extern __shared__ uint32_t smg4[];
    uint32_t* Asm = smg4;               // 2 * ASZ
    uint32_t* Bsm = smg4 + 2 * ASZ;     // 2 * BSZ32

    int tid = threadIdx.x;
    int mb = blockIdx.x * BM, nb = blockIdx.y * BN;
    int warp = tid >> 5, lane = tid & 31;
    int wm = warp & 3, wn = warp >> 2;         // 4m x 2n warp grid, warp = 64x32
    int g = lane >> 2, tig = lane & 3;

    // fp32-A gather indices (MODE 1)
    int arow8 = tid >> 3, acol8 = (tid & 7) * 4;
    int asrc[8];
    if (!ABF) {
        #pragma unroll
        for (int p = 0; p < 8; p++) {
            int r = mb + arow8 + p * 32;
            int win = r >> 8, t = r & 255;
            int bb = win >> 8, wi = win & 255;
            int wr = wi >> 4,  wc = wi & 15;
            int rr = t  >> 4,  cc = t  & 15;
            asrc[p] = bb * 65536 + (wr * 16 + rr) * 256 + (wc * 16 + cc);
        }
    }

    uint32_t sA = (uint32_t)__cvta_generic_to_shared(Asm);
    uint32_t sB = (uint32_t)__cvta_generic_to_shared(Bsm);
    int brow = tid >> 2, bchunk = tid & 3;

    auto issue = [&](int it, int buf) {
        int k0 = it * 32;
        if (ABF) {
            const __nv_bfloat16* A = (const __nv_bfloat16*)Av;
            uint32_t da = sA + (uint32_t)(buf * ASZ) * 4u;
            #pragma unroll
            for (int p = 0; p < 4; p++) {
                int r = brow + p * 64;
                cp16(da + (uint32_t)(r * BAS + bchunk * 4) * 4u,
                     A + (size_t)(mb + r) * K + k0 + bchunk * 8);
            }
        } else {
            const float* A = (const float*)Av;
            uint32_t da = sA + (uint32_t)(buf * ASZ) * 4u;
            #pragma unroll
            for (int p = 0; p < 8; p++)
                cp16(da + (uint32_t)((arow8 + p * 32) * FAS + acol8) * 4u,
                     A + (size_t)asrc[p] * K + k0 + acol8);
        }
        uint32_t db = sB + (uint32_t)(buf * BSZ32) * 4u;
        cp16(db + (uint32_t)(brow * BAS + bchunk * 4) * 4u,
             W + (size_t)(nb + brow) * K + k0 + bchunk * 8);
    };

    float acc[4][4][4];
    #pragma unroll
    for (int mt = 0; mt < 4; mt++)
        #pragma unroll
        for (int nt = 0; nt < 4; nt++)
            #pragma unroll
            for (int i = 0; i < 4; i++) acc[mt][nt][i] = 0.f;

    issue(0, 0); CP_COMMIT();

    for (int it = 0; it < NIT; it++) {
        int buf = it & 1;
        if (it + 1 < NIT) { issue(it + 1, buf ^ 1); CP_COMMIT(); CP_WAIT1(); }
        else             { CP_WAIT0(); }
        __syncthreads();

        const uint32_t* as4 = Asm + buf * ASZ;
        const uint32_t* bs4 = Bsm + buf * BSZ32;
        const float* asf = (const float*)as4;
        #pragma unroll
        for (int ks = 0; ks < 2; ks++) {
            uint32_t a[4][4], b[4][2];
            #pragma unroll
            for (int mt = 0; mt < 4; mt++) {
                int r0 = wm * 64 + mt * 16;
                if (ABF) {
                    const uint32_t* pr = as4 + (r0 + g) * BAS + 8 * ks + tig;
                    a[mt][0] = pr[0];
                    a[mt][1] = pr[8 * BAS];
                    a[mt][2] = pr[4];
                    a[mt][3] = pr[8 * BAS + 4];
                } else {
                    const float* pr = asf + (r0 + g) * FAS + 16 * ks + tig * 2;
                    float2 v0 = *(const float2*)pr;
                    float2 v1 = *(const float2*)(pr + 8 * FAS);
                    float2 v2 = *(const float2*)(pr + 8);
                    float2 v3 = *(const float2*)(pr + 8 * FAS + 8);
                    a[mt][0] = packbf(v0.x, v0.y);
                    a[mt][1] = packbf(v1.x, v1.y);
                    a[mt][2] = packbf(v2.x, v2.y);
                    a[mt][3] = packbf(v3.x, v3.y);
                }
            }
            #pragma unroll
            for (int nt = 0; nt < 4; nt++) {
                const uint32_t* pc = bs4 + (wn * 32 + nt * 8 + g) * BAS + 8 * ks + tig;
                b[nt][0] = pc[0];
                b[nt][1] = pc[4];
            }
            #pragma unroll
            for (int mt = 0; mt < 4; mt++)
                #pragma unroll
                for (int nt = 0; nt < 4; nt++)
                    mma_bf16(acc[mt][nt], a[mt], b[nt]);
        }
        __syncthreads();
    }

    #pragma unroll
    for (int mt = 0; mt < 4; mt++) {
        #pragma unroll
        for (int half = 0; half < 2; half++) {
            int row = mb + wm * 64 + mt * 16 + g + half * 8;
            int nat = row;
            if (MODE == 2) {
                int win = row >> 6, t = row & 63;
                int bI = win >> 8, wi = win & 255;
                int wr = wi >> 4,  wc = wi & 15;
                int rr = t  >> 3,  cc = t  & 7;
                nat = bI * 16384 + (wr * 8 + rr) * 128 + (wc * 8 + cc);
            }
            #pragma unroll
            for (int nt = 0; nt < 4; nt++) {
                int col = nb + wn * 32 + nt * 8 + tig * 2;
                float ox = acc[mt][nt][half * 2 + 0] + bias[col];
                float oy = acc[mt][nt][half * 2 + 1] + bias[col + 1];
                if (MODE == 2) {
                    float* C = (float*)Cv;
                    float2 s = *(const float2*)(add + (size_t)nat * DIM + col);
                    *(float2*)(C + (size_t)nat * DIM + col) = make_float2(ox + s.x, oy + s.y);
                } else if (MODE == 4) {
                    float* C = (float*)Cv;
                    float2 s = *(const float2*)(add + (size_t)row * N + col);
                    *(float2*)(C + (size_t)row * N + col) = make_float2(ox + s.x, oy + s.y);
                } else {
                    if (MODE == 3) {
                        ox = 0.5f * ox * (1.0f + erff(ox * 0.70710678118654752f));
                        oy = 0.5f * oy * (1.0f + erff(oy * 0.70710678118654752f));
                    }
                    __nv_bfloat16* C = (__nv_bfloat16*)Cv;
                    *(uint32_t*)(C + (size_t)row * N + col) = packbf(ox, oy);
                }
            }
        }
    }
}

// ---------------- Attention v4: all-bf16 fragments, shuffle-free PV -----------
// 128 threads = 4 warps per (window, head). Warp w owns q-rows 16w..16w+15 and
// all 256 KV. S (16x256) in fp32 accumulators; P->A-fragment is a pure pack
// (accumulator col layout {2t,2t+1} == bf16 A-fragment layout). No shuffles.
#define AQS 20      // u32 row stride for Q/K (16 data + 4 pad)
#define AVS 132     // u32 row stride for VT (128 data + 4 pad)
#define OFFK  1280
#define OFFVT 6400
#define OFFB  10624
#define ATTN_SMEM_BYTES ((10624 + 532) * 4)

__global__ __launch_bounds__(128) void attn_kernel(const float* __restrict__ rel_bias)
{
    extern __shared__ uint32_t sm4[];
    uint32_t* sQp  = sm4;            // 64 x 20
    uint32_t* sKp  = sm4 + OFFK;     // 256 x 20
    uint32_t* sVTp = sm4 + OFFVT;    // 32 x 132 : VT[d][j2] = {V[2j2][d], V[2j2+1][d]}
    float*    sB   = (float*)(sm4 + OFFB);   // 529

    int win = blockIdx.x, h = blockIdx.y;
    int tid = threadIdx.x;

    for (int r = tid; r < 529; r += 128) sB[r] = rel_bias[r * HEADS + h];

    const __nv_bfloat16* qb = g_q + (size_t)win * 64 * DIM + h * HD;
    #pragma unroll
    for (int it = 0; it < 2; it++) {
        int id = tid + it * 128;               // 0..255
        int row = id >> 2, c = id & 3;
        uint4 v = *(const uint4*)(qb + (size_t)row * DIM + c * 8);
        *(uint4*)&sQp[row * AQS + c * 4] = v;
    }
    const __nv_bfloat16* kb = g_kv + (size_t)win * 256 * (2 * DIM) + h * HD;
    const __nv_bfloat16* vb = kb + DIM;
    #pragma unroll
    for (int it = 0; it < 8; it++) {
        int id = tid + it * 128;               // 0..1023
        int row = id >> 2, c = id & 3;
        uint4 v = *(const uint4*)(kb + (size_t)row * (2 * DIM) + c * 8);
        *(uint4*)&sKp[row * AQS + c * 4] = v;
    }
    // V: thread = j2 (0..127), it = d-chunk
    #pragma unroll
    for (int c = 0; c < 4; c++) {
        int j2 = tid;
        uint4 r0 = *(const uint4*)(vb + (size_t)(2 * j2) * (2 * DIM) + c * 8);
        uint4 r1 = *(const uint4*)(vb + (size_t)(2 * j2 + 1) * (2 * DIM) + c * 8);
        const uint32_t* x = (const uint32_t*)&r0;
        const uint32_t* y = (const uint32_t*)&r1;
        #pragma unroll
        for (int dd = 0; dd < 4; dd++) {
            sVTp[(c * 8 + 2 * dd + 0) * AVS + j2] = __byte_perm(x[dd], y[dd], 0x5410);
            sVTp[(c * 8 + 2 * dd + 1) * AVS + j2] = __byte_perm(x[dd], y[dd], 0x7632);
        }
    }
    __syncthreads();

    int warp = tid >> 5, lane = tid & 31;
    int g = lane >> 2, tig = lane & 3;
    int r0 = warp * 16;

    // ---- QK: S = Q @ K^T (two k16 steps), 16x256 in registers
    float acc[32][4];
    #pragma unroll
    for (int nt = 0; nt < 32; nt++)
        #pragma unroll
        for (int i = 0; i < 4; i++) acc[nt][i] = 0.f;

    #pragma unroll
    for (int ks = 0; ks < 2; ks++) {
        const uint32_t* pq = sQp + (r0 + g) * AQS + 8 * ks + tig;
        uint32_t a[4];
        a[0] = pq[0];
        a[1] = pq[8 * AQS];
        a[2] = pq[4];
        a[3] = pq[8 * AQS + 4];
        #pragma unroll
        for (int nt = 0; nt < 32; nt++) {
            const uint32_t* pk = sKp + (nt * 8 + g) * AQS + 8 * ks + tig;
            uint32_t b[2] = {pk[0], pk[4]};
            mma_bf16(acc[nt], a, b);
        }
    }

    // ---- scale + bias: ridx = 23*(i>>3)+(i&7)+360 - 23*(j>>4)-(j&15)
    int i_lo = r0 + g, i_hi = i_lo + 8;
    int xlo = (i_lo >> 3) * 23 + (i_lo & 7) + 360;
    int xhi = (i_hi >> 3) * 23 + (i_hi & 7) + 360;
    #pragma unroll
    for (int nt = 0; nt < 32; nt++) {
        int j0 = nt * 8 + tig * 2, j1 = j0 + 1;
        int y0 = 23 * (j0 >> 4) + (j0 & 15);
        int y1 = 23 * (j1 >> 4) + (j1 & 15);
        acc[nt][0] = acc[nt][0] * SCALE + sB[xlo - y0];
        acc[nt][1] = acc[nt][1] * SCALE + sB[xlo - y1];
        acc[nt][2] = acc[nt][2] * SCALE + sB[xhi - y0];
        acc[nt][3] = acc[nt][3] * SCALE + sB[xhi - y1];
    }

    // ---- softmax, quad-shuffle reductions only
    float mlo = -1e30f, mhi = -1e30f;
    #pragma unroll
    for (int nt = 0; nt < 32; nt++) {
        mlo = fmaxf(mlo, fmaxf(acc[nt][0], acc[nt][1]));
        mhi = fmaxf(mhi, fmaxf(acc[nt][2], acc[nt][3]));
    }
    #pragma unroll
    for (int off = 1; off < 4; off <<= 1) {
        mlo = fmaxf(mlo, __shfl_xor_sync(0xffffffffu, mlo, off));
        mhi = fmaxf(mhi, __shfl_xor_sync(0xffffffffu, mhi, off));
    }
    float slo = 0.f, shi = 0.f;
    #pragma unroll
    for (int nt = 0; nt < 32; nt++) {
        acc[nt][0] = __expf(acc[nt][0] - mlo); slo += acc[nt][0];
        acc[nt][1] = __expf(acc[nt][1] - mlo); slo += acc[nt][1];
        acc[nt][2] = __expf(acc[nt][2] - mhi); shi += acc[nt][2];
        acc[nt][3] = __expf(acc[nt][3] - mhi); shi += acc[nt][3];
    }
    #pragma unroll
    for (int off = 1; off < 4; off <<= 1) {
        slo += __shfl_xor_sync(0xffffffffu, slo, off);
        shi += __shfl_xor_sync(0xffffffffu, shi, off);
    }
    float invlo = 1.0f / slo, invhi = 1.0f / shi;
    #pragma unroll
    for (int nt = 0; nt < 32; nt++) {
        acc[nt][0] *= invlo; acc[nt][1] *= invlo;
        acc[nt][2] *= invhi; acc[nt][3] *= invhi;
    }

    // ---- PV: O = P @ V. P accumulator IS the bf16 A-fragment (pack only).
    float o[4][4];
    #pragma unroll
    for (int nt = 0; nt < 4; nt++)
        #pragma unroll
        for (int i = 0; i < 4; i++) o[nt][i] = 0.f;

    #pragma unroll
    for (int kc = 0; kc < 16; kc++) {
        uint32_t a[4];
        a[0] = packbf(acc[2 * kc][0],     acc[2 * kc][1]);
        a[1] = packbf(acc[2 * kc][2],     acc[2 * kc][3]);
        a[2] = packbf(acc[2 * kc + 1][0], acc[2 * kc + 1][1]);
        a[3] = packbf(acc[2 * kc + 1][2], acc[2 * kc + 1][3]);
        #pragma unroll
        for (int nt = 0; nt < 4; nt++) {
            const uint32_t* pv = sVTp + (nt * 8 + g) * AVS + 8 * kc + tig;
            uint32_t b[2] = {pv[0], pv[4]};
            mma_bf16(o[nt], a, b);
        }
    }

    // ---- store O (bf16)
    __nv_bfloat16* ob = g_ao + (size_t)win * 64 * DIM + h * HD;
    #pragma unroll
    for (int nt = 0; nt < 4; nt++) {
        int col = nt * 8 + tig * 2;
        *(uint32_t*)(ob + (size_t)i_lo * DIM + col) = packbf(o[nt][0], o[nt][1]);
        *(uint32_t*)(ob + (size_t)i_hi * DIM + col) = packbf(o[nt][2], o[nt][3]);
    }
}

// ---------------- launch ----------------
extern "C" void kernel_launch(void* const* d_in, const int* in_sizes, int n_in,
                              void* d_out, int out_size)
{
    const float* x     = (const float*)d_in[0];
    const float* x2    = (const float*)d_in[1];
    const float* n1w   = (const float*)d_in[2];
    const float* n1b   = (const float*)d_in[3];
    const float* qkvw  = (const float*)d_in[4];
    const float* qkvb  = (const float*)d_in[5];
    const float* qkv2w = (const float*)d_in[6];
    const float* qkv2b = (const float*)d_in[7];
    const float* relb  = (const float*)d_in[8];
    const float* projw = (const float*)d_in[9];
    const float* projb = (const float*)d_in[10];
    const float* n2w   = (const float*)d_in[11];
    const float* n2b   = (const float*)d_in[12];
    const float* fc1w  = (const float*)d_in[13];
    const float* fc1b  = (const float*)d_in[14];
    const float* fc2w  = (const float*)d_in[15];
    const float* fc2b  = (const float*)d_in[16];
    float* out = (float*)d_out;

    __nv_bfloat16 *p_xn, *p_q, *p_kv, *p_ao, *p_ln2, *p_h;
    __nv_bfloat16 *p_wq, *p_wkv, *p_wp, *p_w1, *p_w2;
    float *p_x1;
    cudaGetSymbolAddress((void**)&p_xn,  g_xn);
    cudaGetSymbolAddress((void**)&p_q,   g_q);
    cudaGetSymbolAddress((void**)&p_kv,  g_kv);
    cudaGetSymbolAddress((void**)&p_ao,  g_ao);
    cudaGetSymbolAddress((void**)&p_x1,  g_x1);
    cudaGetSymbolAddress((void**)&p_ln2, g_ln2);
    cudaGetSymbolAddress((void**)&p_h,   g_h);
    cudaGetSymbolAddress((void**)&p_wq,  g_wq);
    cudaGetSymbolAddress((void**)&p_wkv, g_wkv);
    cudaGetSymbolAddress((void**)&p_wp,  g_wp);
    cudaGetSymbolAddress((void**)&p_w1,  g_w1);
    cudaGetSymbolAddress((void**)&p_w2,  g_w2);

    cudaFuncSetAttribute(attn_kernel, cudaFuncAttributeMaxDynamicSharedMemorySize, ATTN_SMEM_BYTES);
    cudaFuncSetAttribute(gemm_bf16<0, 192, 192, true >, cudaFuncAttributeMaxDynamicSharedMemorySize, SM_BF);
    cudaFuncSetAttribute(gemm_bf16<1, 384, 192, false>, cudaFuncAttributeMaxDynamicSharedMemorySize, SM_FP);
    cudaFuncSetAttribute(gemm_bf16<2, 192, 192, true >, cudaFuncAttributeMaxDynamicSharedMemorySize, SM_BF);
    cudaFuncSetAttribute(gemm_bf16<3, 768, 192, true >, cudaFuncAttributeMaxDynamicSharedMemorySize, SM_BF);
    cudaFuncSetAttribute(gemm_bf16<4, 192, 768, true >, cudaFuncAttributeMaxDynamicSharedMemorySize, SM_BF);

    // 0. weights -> bf16
    cvt_w<<<(192*192/4 + 255)/256, 256>>>(qkvw,  p_wq,  192*192/4);
    cvt_w<<<(384*192/4 + 255)/256, 256>>>(qkv2w, p_wkv, 384*192/4);
    cvt_w<<<(192*192/4 + 255)/256, 256>>>(projw, p_wp,  192*192/4);
    cvt_w<<<(768*192/4 + 255)/256, 256>>>(fc1w,  p_w1,  768*192/4);
    cvt_w<<<(192*768/4 + 255)/256, 256>>>(fc2w,  p_w2,  192*768/4);

    // 1. LN1 + window partition (bf16 out)
    ln_kernel<0><<<NQTOK, 192>>>(x, n1w, n1b, p_xn);
    // 2. q projection
    gemm_bf16<0, 192, 192, true><<<dim3(256, 3), 256, SM_BF>>>(p_xn, p_wq, qkvb, p_q, nullptr);
    // 3. kv projection (gather x2 fp32 through 16x16 windows)
    gemm_bf16<1, 384, 192, false><<<dim3(1024, 6), 256, SM_FP>>>(x2, p_wkv, qkv2b, p_kv, nullptr);
    // 4. windowed cross attention
    attn_kernel<<<dim3(NWIN, HEADS), 128, ATTN_SMEM_BYTES>>>(relb);
    // 5. output projection + shortcut + window reverse (fp32 out)
    gemm_bf16<2, 192, 192, true><<<dim3(256, 3), 256, SM_BF>>>(p_ao, p_wp, projb, p_x1, x);
    // 6. LN2 (bf16 out)
    ln_kernel<1><<<NQTOK, 192>>>(p_x1, n2w, n2b, p_ln2);
    // 7. fc1 + gelu
    gemm_bf16<3, 768, 192, true><<<dim3(256, 12), 256, SM_BF>>>(p_ln2, p_w1, fc1b, p_h, nullptr);
    // 8. fc2 + residual -> output (fp32)
    gemm_bf16<4, 192, 768, true><<<dim3(256, 3), 256, SM_BF>>>(p_h, p_w2, fc2b, out, p_x1);
}

// round 11
// speedup vs baseline: 1.4677x; 1.0900x over previous
#include <cuda_runtime.h>
#include <cuda_bf16.h>
#include <math.h>
#include <stdint.h>

#define DIM   192
#define HEADS 6
#define HD    32
#define NWIN  1024          // 4 * 16 * 16
#define NQTOK 65536         // 1024 * 64  (== B*L)
#define NKVTOK 262144       // 1024 * 256
#define SCALE 0.17677669529663687f   // 32^-0.5

// ---------------- scratch (device globals; no runtime allocation) ----------------
__device__ __nv_bfloat16 g_xn [(size_t)NQTOK * DIM];      // LN1 out, window order
__device__ __nv_bfloat16 g_q  [(size_t)NQTOK * DIM];      // q projection
__device__ __nv_bfloat16 g_kv [(size_t)NKVTOK * 2 * DIM]; // k | v, window order
__device__ __nv_bfloat16 g_ao [(size_t)NQTOK * DIM];      // attention output
__device__ float         g_x1 [(size_t)NQTOK * DIM];      // x after first residual (fp32)
__device__ __nv_bfloat16 g_ln2[(size_t)NQTOK * DIM];      // LN2 output
__device__ __nv_bfloat16 g_h  [(size_t)NQTOK * 4 * DIM];  // gelu(fc1) output
// bf16 weights (pre-converted once per launch)
__device__ __nv_bfloat16 g_wq [192 * 192];
__device__ __nv_bfloat16 g_wkv[384 * 192];
__device__ __nv_bfloat16 g_wp [192 * 192];
__device__ __nv_bfloat16 g_w1 [768 * 192];
__device__ __nv_bfloat16 g_w2 [192 * 768];

// ---------------- helpers ----------------
__device__ __forceinline__ void mma_bf16(float* d, const uint32_t* a, const uint32_t* b) {
    asm volatile(
        "mma.sync.aligned.m16n8k16.row.col.f32.bf16.bf16.f32 "
        "{%0,%1,%2,%3}, {%4,%5,%6,%7}, {%8,%9}, {%0,%1,%2,%3};\n"
        : "+f"(d[0]), "+f"(d[1]), "+f"(d[2]), "+f"(d[3])
        : "r"(a[0]), "r"(a[1]), "r"(a[2]), "r"(a[3]),
          "r"(b[0]), "r"(b[1]));
}
// pack: lo half = x (first k), hi half = y
__device__ __forceinline__ uint32_t packbf(float x, float y) {
    uint32_t r;
    asm("cvt.rn.bf16x2.f32 %0, %1, %2;" : "=r"(r) : "f"(y), "f"(x));
    return r;
}
__device__ __forceinline__ void cp16(uint32_t dst, const void* src) {
    asm volatile("cp.async.cg.shared.global [%0], [%1], 16;\n" :: "r"(dst), "l"(src));
}
#define CP_COMMIT() asm volatile("cp.async.commit_group;\n")
#define CP_WAIT1()  asm volatile("cp.async.wait_group 1;\n")
#define CP_WAIT0()  asm volatile("cp.async.wait_group 0;\n")

// ---------------- all weights fp32 -> bf16 in ONE launch ----------------
// segment sizes in float4 units: 9216, 18432, 9216, 36864, 36864 (cum 110592)
__global__ __launch_bounds__(256) void cvt_all(
    const float* __restrict__ s0, const float* __restrict__ s1,
    const float* __restrict__ s2, const float* __restrict__ s3,
    const float* __restrict__ s4)
{
    int i = blockIdx.x * 256 + threadIdx.x;
    const float* s; __nv_bfloat16* d; int base;
    if      (i <  9216) { s = s0; d = g_wq;  base = 0; }
    else if (i < 27648) { s = s1; d = g_wkv; base = 9216; }
    else if (i < 36864) { s = s2; d = g_wp;  base = 27648; }
    else if (i < 73728) { s = s3; d = g_w1;  base = 36864; }
    else                { s = s4; d = g_w2;  base = 73728; }
    int j = i - base;
    float4 v = ((const float4*)s)[j];
    uint2 o;
    o.x = packbf(v.x, v.y);
    o.y = packbf(v.z, v.w);
    ((uint2*)d)[j] = o;
}

// ---------------- LayerNorm: warp per token, 8 tokens/block ----------------
template<int MODE>
__global__ __launch_bounds__(256) void ln_kernel(
    const float* __restrict__ x, const float* __restrict__ w,
    const float* __restrict__ b, __nv_bfloat16* __restrict__ out)
{
    int warp = threadIdx.x >> 5, lane = threadIdx.x & 31;
    int tok = blockIdx.x * 8 + warp;
    int in_row, out_row;
    if (MODE == 0) {
        int win = tok >> 6, t = tok & 63;
        int bb = win >> 8, wi = win & 255;
        int wr = wi >> 4,  wc = wi & 15;
        int r  = t  >> 3,  c  = t  & 7;
        in_row  = bb * 16384 + (wr * 8 + r) * 128 + (wc * 8 + c);
        out_row = tok;
    } else {
        in_row = out_row = tok;
    }
    const float* xr = x + (size_t)in_row * DIM;
    float v[6];
    float s1 = 0.f, s2 = 0.f;
    #pragma unroll
    for (int i = 0; i < 6; i++) {
        v[i] = xr[lane + i * 32];
        s1 += v[i]; s2 += v[i] * v[i];
    }
    #pragma unroll
    for (int off = 16; off; off >>= 1) {
        s1 += __shfl_xor_sync(0xffffffffu, s1, off);
        s2 += __shfl_xor_sync(0xffffffffu, s2, off);
    }
    float mean = s1 * (1.0f / 192.0f);
    float var  = s2 * (1.0f / 192.0f) - mean * mean;
    float rstd = rsqrtf(var + 1e-5f);
    __nv_bfloat16* orow = out + (size_t)out_row * DIM;
    #pragma unroll
    for (int i = 0; i < 6; i++) {
        int c = lane + i * 32;
        orow[c] = __float2bfloat16((v[i] - mean) * rstd * w[c] + b[c]);
    }
}

// ---------------- BF16 GEMM, BM=256, cp.async multi-stage ----------------
// C = A @ W^T + bias.  W bf16 (N, K) row-major. A bf16 (ABF, 3-stage) or
// fp32 gather (2-stage).
// MODE 0: plain -> bf16.  MODE 1: gather x2 (fp32) through 16x16 windows -> bf16.
// MODE 2: + add[nat_row] -> fp32, window-reversed.  MODE 3: gelu -> bf16.
// MODE 4: + add[row] -> fp32.
#define BAS 20                          // u32 row stride, bf16 A / B tiles
#define FAS 40                          // float row stride, fp32 A tiles
#define BSZ32 (64 * BAS)
#define SM_BF ((3 * 256 * BAS + 3 * BSZ32) * 4)
#define SM_FP ((2 * 256 * FAS + 2 * BSZ32) * 4)

template<int MODE, int N, int K, bool ABF>
__global__ __launch_bounds__(256) void gemm_bf16(
    const void* __restrict__ Av, const __nv_bfloat16* __restrict__ W,
    const float* __restrict__ bias, void* __restrict__ Cv,
    const float* __restrict__ add)
{
    constexpr int BM = 256, BN = 64;
    constexpr int STAGES = ABF ? 3 : 2;
    constexpr int ASZ = ABF ? 256 * BAS : 256 * FAS;   // 4-byte units
    constexpr int NIT = K / 32;
    extern __shared__ uint32_t smg4[];
    uint32_t* Asm = smg4;                       // STAGES * ASZ
    uint32_t* Bsm = smg4 + STAGES * ASZ;        // STAGES * BSZ32

    int tid = threadIdx.x;
    int mb = blockIdx.x * BM, nb = blockIdx.y * BN;
    int warp = tid >> 5, lane = tid & 31;
    int wm = warp & 3, wn = warp >> 2;         // 4m x 2n warp grid, warp = 64x32
    int g = lane >> 2, tig = lane & 3;

    // fp32-A gather indices (MODE 1)
    int arow8 = tid >> 3, acol8 = (tid & 7) * 4;
    int asrc[8];
    if (!ABF) {
        #pragma unroll
        for (int p = 0; p < 8; p++) {
            int r = mb + arow8 + p * 32;
            int win = r >> 8, t = r & 255;
            int bb = win >> 8, wi = win & 255;
            int wr = wi >> 4,  wc = wi & 15;
            int rr = t  >> 4,  cc = t  & 15;
            asrc[p] = bb * 65536 + (wr * 16 + rr) * 256 + (wc * 16 + cc);
        }
    }

    uint32_t sA = (uint32_t)__cvta_generic_to_shared(Asm);
    uint32_t sB = (uint32_t)__cvta_generic_to_shared(Bsm);
    int brow = tid >> 2, bchunk = tid & 3;

    auto issue = [&](int it, int buf) {
        int k0 = it * 32;
        if (ABF) {
            const __nv_bfloat16* A = (const __nv_bfloat16*)Av;
            uint32_t da = sA + (uint32_t)(buf * ASZ) * 4u;
            #pragma unroll
            for (int p = 0; p < 4; p++) {
                int r = brow + p * 64;
                cp16(da + (uint32_t)(r * BAS + bchunk * 4) * 4u,
                     A + (size_t)(mb + r) * K + k0 + bchunk * 8);
            }
        } else {
            const float* A = (const float*)Av;
            uint32_t da = sA + (uint32_t)(buf * ASZ) * 4u;
            #pragma unroll
            for (int p = 0; p < 8; p++)
                cp16(da + (uint32_t)((arow8 + p * 32) * FAS + acol8) * 4u,
                     A + (size_t)asrc[p] * K + k0 + acol8);
        }
        uint32_t db = sB + (uint32_t)(buf * BSZ32) * 4u;
        cp16(db + (uint32_t)(brow * BAS + bchunk * 4) * 4u,
             W + (size_t)(nb + brow) * K + k0 + bchunk * 8);
    };

    float acc[4][4][4];
    #pragma unroll
    for (int mt = 0; mt < 4; mt++)
        #pragma unroll
        for (int nt = 0; nt < 4; nt++)
            #pragma unroll
            for (int i = 0; i < 4; i++) acc[mt][nt][i] = 0.f;

    issue(0, 0); CP_COMMIT();
    if (STAGES == 3) { issue(1, 1); CP_COMMIT(); }

    for (int it = 0; it < NIT; it++) {
        int buf = it % STAGES;
        if (STAGES == 3) {
            if (it + 1 < NIT) CP_WAIT1(); else CP_WAIT0();
        } else {
            if (it + 1 < NIT) { issue(it + 1, (it + 1) & 1); CP_COMMIT(); CP_WAIT1(); }
            else              { CP_WAIT0(); }
        }
        __syncthreads();

        const uint32_t* as4 = Asm + buf * ASZ;
        const uint32_t* bs4 = Bsm + buf * BSZ32;
        const float* asf = (const float*)as4;
        #pragma unroll
        for (int ks = 0; ks < 2; ks++) {
            uint32_t a[4][4], b[4][2];
            #pragma unroll
            for (int mt = 0; mt < 4; mt++) {
                int r0 = wm * 64 + mt * 16;
                if (ABF) {
                    const uint32_t* pr = as4 + (r0 + g) * BAS + 8 * ks + tig;
                    a[mt][0] = pr[0];
                    a[mt][1] = pr[8 * BAS];
                    a[mt][2] = pr[4];
                    a[mt][3] = pr[8 * BAS + 4];
                } else {
                    const float* pr = asf + (r0 + g) * FAS + 16 * ks + tig * 2;
                    float2 v0 = *(const float2*)pr;
                    float2 v1 = *(const float2*)(pr + 8 * FAS);
                    float2 v2 = *(const float2*)(pr + 8);
                    float2 v3 = *(const float2*)(pr + 8 * FAS + 8);
                    a[mt][0] = packbf(v0.x, v0.y);
                    a[mt][1] = packbf(v1.x, v1.y);
                    a[mt][2] = packbf(v2.x, v2.y);
                    a[mt][3] = packbf(v3.x, v3.y);
                }
            }
            #pragma unroll
            for (int nt = 0; nt < 4; nt++) {
                const uint32_t* pc = bs4 + (wn * 32 + nt * 8 + g) * BAS + 8 * ks + tig;
                b[nt][0] = pc[0];
                b[nt][1] = pc[4];
            }
            #pragma unroll
            for (int mt = 0; mt < 4; mt++)
                #pragma unroll
                for (int nt = 0; nt < 4; nt++)
                    mma_bf16(acc[mt][nt], a[mt], b[nt]);
        }
        __syncthreads();
        if (STAGES == 3 && it + 2 < NIT) { issue(it + 2, (it + 2) % 3); CP_COMMIT(); }
    }

    #pragma unroll
    for (int mt = 0; mt < 4; mt++) {
        #pragma unroll
        for (int half = 0; half < 2; half++) {
            int row = mb + wm * 64 + mt * 16 + g + half * 8;
            int nat = row;
            if (MODE == 2) {
                int win = row >> 6, t = row & 63;
                int bI = win >> 8, wi = win & 255;
                int wr = wi >> 4,  wc = wi & 15;
                int rr = t  >> 3,  cc = t  & 7;
                nat = bI * 16384 + (wr * 8 + rr) * 128 + (wc * 8 + cc);
            }
            #pragma unroll
            for (int nt = 0; nt < 4; nt++) {
                int col = nb + wn * 32 + nt * 8 + tig * 2;
                float ox = acc[mt][nt][half * 2 + 0] + bias[col];
                float oy = acc[mt][nt][half * 2 + 1] + bias[col + 1];
                if (MODE == 2) {
                    float* C = (float*)Cv;
                    float2 s = *(const float2*)(add + (size_t)nat * DIM + col);
                    *(float2*)(C + (size_t)nat * DIM + col) = make_float2(ox + s.x, oy + s.y);
                } else if (MODE == 4) {
                    float* C = (float*)Cv;
                    float2 s = *(const float2*)(add + (size_t)row * N + col);
                    *(float2*)(C + (size_t)row * N + col) = make_float2(ox + s.x, oy + s.y);
                } else {
                    if (MODE == 3) {
                        ox = 0.5f * ox * (1.0f + erff(ox * 0.70710678118654752f));
                        oy = 0.5f * oy * (1.0f + erff(oy * 0.70710678118654752f));
                    }
                    __nv_bfloat16* C = (__nv_bfloat16*)Cv;
                    *(uint32_t*)(C + (size_t)row * N + col) = packbf(ox, oy);
                }
            }
        }
    }
}

// ---------------- Attention v4: all-bf16 fragments, shuffle-free PV -----------
// 128 threads = 4 warps per (window, head). Warp w owns q-rows 16w..16w+15 and
// all 256 KV. S (16x256) in fp32 accumulators; P->A-fragment is a pure pack
// (accumulator col layout {2t,2t+1} == bf16 A-fragment layout). No shuffles.
#define AQS 20      // u32 row stride for Q/K (16 data + 4 pad)
#define AVS 132     // u32 row stride for VT (128 data + 4 pad)
#define OFFK  1280
#define OFFVT 6400
#define OFFB  10624
#define ATTN_SMEM_BYTES ((10624 + 532) * 4)

__global__ __launch_bounds__(128) void attn_kernel(const float* __restrict__ rel_bias)
{
    extern __shared__ uint32_t sm4[];
    uint32_t* sQp  = sm4;            // 64 x 20
    uint32_t* sKp  = sm4 + OFFK;     // 256 x 20
    uint32_t* sVTp = sm4 + OFFVT;    // 32 x 132 : VT[d][j2] = {V[2j2][d], V[2j2+1][d]}
    float*    sB   = (float*)(sm4 + OFFB);   // 529

    int win = blockIdx.x, h = blockIdx.y;
    int tid = threadIdx.x;

    for (int r = tid; r < 529; r += 128) sB[r] = rel_bias[r * HEADS + h];

    const __nv_bfloat16* qb = g_q + (size_t)win * 64 * DIM + h * HD;
    #pragma unroll
    for (int it = 0; it < 2; it++) {
        int id = tid + it * 128;               // 0..255
        int row = id >> 2, c = id & 3;
        uint4 v = *(const uint4*)(qb + (size_t)row * DIM + c * 8);
        *(uint4*)&sQp[row * AQS + c * 4] = v;
    }
    const __nv_bfloat16* kb = g_kv + (size_t)win * 256 * (2 * DIM) + h * HD;
    const __nv_bfloat16* vb = kb + DIM;
    #pragma unroll
    for (int it = 0; it < 8; it++) {
        int id = tid + it * 128;               // 0..1023
        int row = id >> 2, c = id & 3;
        uint4 v = *(const uint4*)(kb + (size_t)row * (2 * DIM) + c * 8);
        *(uint4*)&sKp[row * AQS + c * 4] = v;
    }
    // V: thread = j2 (0..127), c = d-chunk
    #pragma unroll
    for (int c = 0; c < 4; c++) {
        int j2 = tid;
        uint4 r0 = *(const uint4*)(vb + (size_t)(2 * j2) * (2 * DIM) + c * 8);
        uint4 r1 = *(const uint4*)(vb + (size_t)(2 * j2 + 1) * (2 * DIM) + c * 8);
        const uint32_t* x = (const uint32_t*)&r0;
        const uint32_t* y = (const uint32_t*)&r1;
        #pragma unroll
        for (int dd = 0; dd < 4; dd++) {
            sVTp[(c * 8 + 2 * dd + 0) * AVS + j2] = __byte_perm(x[dd], y[dd], 0x5410);
            sVTp[(c * 8 + 2 * dd + 1) * AVS + j2] = __byte_perm(x[dd], y[dd], 0x7632);
        }
    }
    __syncthreads();

    int warp = tid >> 5, lane = tid & 31;
    int g = lane >> 2, tig = lane & 3;
    int r0 = warp * 16;

    // ---- QK: S = Q @ K^T (two k16 steps), 16x256 in registers
    float acc[32][4];
    #pragma unroll
    for (int nt = 0; nt < 32; nt++)
        #pragma unroll
        for (int i = 0; i < 4; i++) acc[nt][i] = 0.f;

    #pragma unroll
    for (int ks = 0; ks < 2; ks++) {
        const uint32_t* pq = sQp + (r0 + g) * AQS + 8 * ks + tig;
        uint32_t a[4];
        a[0] = pq[0];
        a[1] = pq[8 * AQS];
        a[2] = pq[4];
        a[3] = pq[8 * AQS + 4];
        #pragma unroll
        for (int nt = 0; nt < 32; nt++) {
            const uint32_t* pk = sKp + (nt * 8 + g) * AQS + 8 * ks + tig;
            uint32_t b[2] = {pk[0], pk[4]};
            mma_bf16(acc[nt], a, b);
        }
    }

    // ---- scale + bias: ridx = 23*(i>>3)+(i&7)+360 - 23*(j>>4)-(j&15)
    int i_lo = r0 + g, i_hi = i_lo + 8;
    int xlo = (i_lo >> 3) * 23 + (i_lo & 7) + 360;
    int xhi = (i_hi >> 3) * 23 + (i_hi & 7) + 360;
    #pragma unroll
    for (int nt = 0; nt < 32; nt++) {
        int j0 = nt * 8 + tig * 2, j1 = j0 + 1;
        int y0 = 23 * (j0 >> 4) + (j0 & 15);
        int y1 = 23 * (j1 >> 4) + (j1 & 15);
        acc[nt][0] = acc[nt][0] * SCALE + sB[xlo - y0];
        acc[nt][1] = acc[nt][1] * SCALE + sB[xlo - y1];
        acc[nt][2] = acc[nt][2] * SCALE + sB[xhi - y0];
        acc[nt][3] = acc[nt][3] * SCALE + sB[xhi - y1];
    }

    // ---- softmax, quad-shuffle reductions only
    float mlo = -1e30f, mhi = -1e30f;
    #pragma unroll
    for (int nt = 0; nt < 32; nt++) {
        mlo = fmaxf(mlo, fmaxf(acc[nt][0], acc[nt][1]));
        mhi = fmaxf(mhi, fmaxf(acc[nt][2], acc[nt][3]));
    }
    #pragma unroll
    for (int off = 1; off < 4; off <<= 1) {
        mlo = fmaxf(mlo, __shfl_xor_sync(0xffffffffu, mlo, off));
        mhi = fmaxf(mhi, __shfl_xor_sync(0xffffffffu, mhi, off));
    }
    float slo = 0.f, shi = 0.f;
    #pragma unroll
    for (int nt = 0; nt < 32; nt++) {
        acc[nt][0] = __expf(acc[nt][0] - mlo); slo += acc[nt][0];
        acc[nt][1] = __expf(acc[nt][1] - mlo); slo += acc[nt][1];
        acc[nt][2] = __expf(acc[nt][2] - mhi); shi += acc[nt][2];
        acc[nt][3] = __expf(acc[nt][3] - mhi); shi += acc[nt][3];
    }
    #pragma unroll
    for (int off = 1; off < 4; off <<= 1) {
        slo += __shfl_xor_sync(0xffffffffu, slo, off);
        shi += __shfl_xor_sync(0xffffffffu, shi, off);
    }
    float invlo = 1.0f / slo, invhi = 1.0f / shi;
    #pragma unroll
    for (int nt = 0; nt < 32; nt++) {
        acc[nt][0] *= invlo; acc[nt][1] *= invlo;
        acc[nt][2] *= invhi; acc[nt][3] *= invhi;
    }

    // ---- PV: O = P @ V. P accumulator IS the bf16 A-fragment (pack only).
    float o[4][4];
    #pragma unroll
    for (int nt = 0; nt < 4; nt++)
        #pragma unroll
        for (int i = 0; i < 4; i++) o[nt][i] = 0.f;

    #pragma unroll
    for (int kc = 0; kc < 16; kc++) {
        uint32_t a[4];
        a[0] = packbf(acc[2 * kc][0],     acc[2 * kc][1]);
        a[1] = packbf(acc[2 * kc][2],     acc[2 * kc][3]);
        a[2] = packbf(acc[2 * kc + 1][0], acc[2 * kc + 1][1]);
        a[3] = packbf(acc[2 * kc + 1][2], acc[2 * kc + 1][3]);
        #pragma unroll
        for (int nt = 0; nt < 4; nt++) {
            const uint32_t* pv = sVTp + (nt * 8 + g) * AVS + 8 * kc + tig;
            uint32_t b[2] = {pv[0], pv[4]};
            mma_bf16(o[nt], a, b);
        }
    }

    // ---- store O (bf16)
    __nv_bfloat16* ob = g_ao + (size_t)win * 64 * DIM + h * HD;
    #pragma unroll
    for (int nt = 0; nt < 4; nt++) {
        int col = nt * 8 + tig * 2;
        *(uint32_t*)(ob + (size_t)i_lo * DIM + col) = packbf(o[nt][0], o[nt][1]);
        *(uint32_t*)(ob + (size_t)i_hi * DIM + col) = packbf(o[nt][2], o[nt][3]);
    }
}

// ---------------- launch ----------------
extern "C" void kernel_launch(void* const* d_in, const int* in_sizes, int n_in,
                              void* d_out, int out_size)
{
    const float* x     = (const float*)d_in[0];
    const float* x2    = (const float*)d_in[1];
    const float* n1w   = (const float*)d_in[2];
    const float* n1b   = (const float*)d_in[3];
    const float* qkvw  = (const float*)d_in[4];
    const float* qkvb  = (const float*)d_in[5];
    const float* qkv2w = (const float*)d_in[6];
    const float* qkv2b = (const float*)d_in[7];
    const float* relb  = (const float*)d_in[8];
    const float* projw = (const float*)d_in[9];
    const float* projb = (const float*)d_in[10];
    const float* n2w   = (const float*)d_in[11];
    const float* n2b   = (const float*)d_in[12];
    const float* fc1w  = (const float*)d_in[13];
    const float* fc1b  = (const float*)d_in[14];
    const float* fc2w  = (const float*)d_in[15];
    const float* fc2b  = (const float*)d_in[16];
    float* out = (float*)d_out;

    __nv_bfloat16 *p_xn, *p_q, *p_kv, *p_ao, *p_ln2, *p_h;
    __nv_bfloat16 *p_wq, *p_wkv, *p_wp, *p_w1, *p_w2;
    float *p_x1;
    cudaGetSymbolAddress((void**)&p_xn,  g_xn);
    cudaGetSymbolAddress((void**)&p_q,   g_q);
    cudaGetSymbolAddress((void**)&p_kv,  g_kv);
    cudaGetSymbolAddress((void**)&p_ao,  g_ao);
    cudaGetSymbolAddress((void**)&p_x1,  g_x1);
    cudaGetSymbolAddress((void**)&p_ln2, g_ln2);
    cudaGetSymbolAddress((void**)&p_h,   g_h);
    cudaGetSymbolAddress((void**)&p_wq,  g_wq);
    cudaGetSymbolAddress((void**)&p_wkv, g_wkv);
    cudaGetSymbolAddress((void**)&p_wp,  g_wp);
    cudaGetSymbolAddress((void**)&p_w1,  g_w1);
    cudaGetSymbolAddress((void**)&p_w2,  g_w2);

    cudaFuncSetAttribute(attn_kernel, cudaFuncAttributeMaxDynamicSharedMemorySize, ATTN_SMEM_BYTES);
    cudaFuncSetAttribute(gemm_bf16<0, 192, 192, true >, cudaFuncAttributeMaxDynamicSharedMemorySize, SM_BF);
    cudaFuncSetAttribute(gemm_bf16<1, 384, 192, false>, cudaFuncAttributeMaxDynamicSharedMemorySize, SM_FP);
    cudaFuncSetAttribute(gemm_bf16<2, 192, 192, true >, cudaFuncAttributeMaxDynamicSharedMemorySize, SM_BF);
    cudaFuncSetAttribute(gemm_bf16<3, 768, 192, true >, cudaFuncAttributeMaxDynamicSharedMemorySize, SM_BF);
    cudaFuncSetAttribute(gemm_bf16<4, 192, 768, true >, cudaFuncAttributeMaxDynamicSharedMemorySize, SM_BF);

    // 0. all weights -> bf16 (one launch; 110592 float4 groups)
    cvt_all<<<432, 256>>>(qkvw, qkv2w, projw, fc1w, fc2w);

    // 1. LN1 + window partition (bf16 out)
    ln_kernel<0><<<NQTOK / 8, 256>>>(x, n1w, n1b, p_xn);
    // 2. q projection
    gemm_bf16<0, 192, 192, true><<<dim3(256, 3), 256, SM_BF>>>(p_xn, p_wq, qkvb, p_q, nullptr);
    // 3. kv projection (gather x2 fp32 through 16x16 windows)
    gemm_bf16<1, 384, 192, false><<<dim3(1024, 6), 256, SM_FP>>>(x2, p_wkv, qkv2b, p_kv, nullptr);
    // 4. windowed cross attention
    attn_kernel<<<dim3(NWIN, HEADS), 128, ATTN_SMEM_BYTES>>>(relb);
    // 5. output projection + shortcut + window reverse (fp32 out)
    gemm_bf16<2, 192, 192, true><<<dim3(256, 3), 256, SM_BF>>>(p_ao, p_wp, projb, p_x1, x);
    // 6. LN2 (bf16 out)
    ln_kernel<1><<<NQTOK / 8, 256>>>(p_x1, n2w, n2b, p_ln2);
    // 7. fc1 + gelu
    gemm_bf16<3, 768, 192, true><<<dim3(256, 12), 256, SM_BF>>>(p_ln2, p_w1, fc1b, p_h, nullptr);
    // 8. fc2 + residual -> output (fp32)
    gemm_bf16<4, 192, 768, true><<<dim3(256, 3), 256, SM_BF>>>(p_h, p_w2, fc2b, out, p_x1);
}